// round 12
// baseline (speedup 1.0000x reference)
#include <cuda_runtime.h>
#include <cstdint>

#define Bq 16
#define Cq 512
#define Nq 4096
#define Kq 64

// ================= scratch (static device allocations only) =================
__device__ uint4 gW16[32][512];            // per-16c-chunk fp16 W images (8KB each)
__device__ float gInvS[Kq][Cq];
__device__ float gCst[Kq];
__device__ float g_sa[(size_t)Bq*Kq*Nq];
__device__ uint4 g_sa16[(size_t)Bq*Kq*256*4];  // [b*64+k][256 chunks][4 q] 16B blocks
__device__ float g_invf[Bq*Kq];
__device__ float g_wx8[8][Bq][Kq][Cq];
__device__ float g_wsum[Bq][Kq];
__device__ float g_row[Bq][Kq];
__device__ float g_nodes[Bq][Kq][Cq];

// ================= helpers =================
__device__ __forceinline__ unsigned pk2h(float lo, float hi) {
    unsigned d;
    asm("cvt.rn.f16x2.f32 %0, %1, %2;" : "=r"(d) : "f"(hi), "f"(lo));
    return d;
}
__device__ __forceinline__ float2 unpk2h(unsigned u) {
    float lo, hi;
    asm("{.reg .f16 a,b; mov.b32 {a,b}, %2; cvt.f32.f16 %0, a; cvt.f32.f16 %1, b;}"
        : "=f"(lo), "=f"(hi) : "r"(u));
    return make_float2(lo, hi);
}
__device__ __forceinline__ unsigned hmul2(unsigned a, unsigned b) {
    unsigned d;
    asm("mul.rn.f16x2 %0, %1, %2;" : "=r"(d) : "r"(a), "r"(b));
    return d;
}
// split pair (v0=even slot, v1=odd slot) into fp16x2 hi and lo regs
__device__ __forceinline__ void splitpair(float v0, float v1, unsigned& h, unsigned& l) {
    h = pk2h(v0, v1);
    float2 f = unpk2h(h);
    l = pk2h(v0 - f.x, v1 - f.y);
}
__device__ __forceinline__ void mmaH(float* d, const unsigned* a, const unsigned* b) {
    asm volatile(
        "mma.sync.aligned.m16n8k16.row.col.f32.f16.f16.f32 "
        "{%0,%1,%2,%3}, {%4,%5,%6,%7}, {%8,%9}, {%0,%1,%2,%3};"
        : "+f"(d[0]), "+f"(d[1]), "+f"(d[2]), "+f"(d[3])
        : "r"(a[0]), "r"(a[1]), "r"(a[2]), "r"(a[3]), "r"(b[0]), "r"(b[1]));
}
__device__ __forceinline__ uint32_t smem_u32(const void* p) {
    uint32_t a;
    asm("{ .reg .u64 t; cvta.to.shared.u64 t, %1; cvt.u32.u64 %0, t; }" : "=r"(a) : "l"(p));
    return a;
}
#define CP16(dst, src) asm volatile("cp.async.cg.shared.global [%0], [%1], 16;" :: "r"(dst), "l"(src))
#define CPCOMMIT()     asm volatile("cp.async.commit_group;" ::: "memory")
#define CPWAIT1()      asm volatile("cp.async.wait_group 1;" ::: "memory")
#define CPWAIT0()      asm volatile("cp.async.wait_group 0;" ::: "memory")

// ===== phase1: 3 bufs of { A raw x [16c][260f pitch], B fp16 image 8KB } =====
#define P1_BUF   24832u
#define P1_BOFF  16640u
#define P1_SMEM  74496
// ===== phase2: 3 bufs of { A raw x [256c][16n] swizzled 16KB, B sa16 4KB } =====
#define P2_BUF   20480u
#define P2_BOFF  16384u
#define P2_SMEM  61440

// ================= prep: sigma, fp16 W images, const =================
__global__ void prep_kernel(const float* __restrict__ anchor,
                            const float* __restrict__ sraw) {
    const int k = blockIdx.x;       // 64
    const int tid = threadIdx.x;    // 256
    float part = 0.f;
#pragma unroll
    for (int jj = 0; jj < 2; ++jj) {
        int c = tid + jj * 256;
        float sr = sraw[k * Cq + c];
        float sg = 1.f / (1.f + __expf(-sr));
        float a  = anchor[k * Cq + c];
        float i2 = 1.f / (sg * sg);
        float w2 = -2.f * a * i2;
        gInvS[k][c] = 1.f / sg;
        part += a * a * i2;
        int ch = c >> 4, cl = c & 15;
        int j = k >> 3, gg = k & 7;
        int q = (cl >> 1) & 3, reg = cl >> 3, half = cl & 1;
        // step0 = x^2 weight (inv_s2), step1 = x weight (-2a*inv_s2)
        float vals[2] = { i2, w2 };
#pragma unroll
        for (int s = 0; s < 2; ++s) {
            unsigned hp, lp;
            splitpair(vals[s], 0.f, hp, lp);
            unsigned short* base =
                (unsigned short*)&gW16[ch][(((s * 8 + j) * 8 + gg) * 4 + q)];
            base[reg * 2 + half]     = (unsigned short)(hp & 0xFFFFu);
            base[4 + reg * 2 + half] = (unsigned short)(lp & 0xFFFFu);
        }
    }
#pragma unroll
    for (int off = 16; off; off >>= 1) part += __shfl_xor_sync(0xffffffffu, part, off);
    __shared__ float red[8];
    if ((tid & 31) == 0) red[tid >> 5] = part;
    __syncthreads();
    if (tid == 0) {
        float s = 0.f;
#pragma unroll
        for (int i = 0; i < 8; ++i) s += red[i];
        gCst[k] = s;
    }
}

// ================= phase 1: distance GEMM (3xFP16 mma) + softmax =================
// block = (n-tile 256, b). warp tile 32n x 64k. 32 chunks of 16 c (2 k16 steps each).
// Passes reordered: x (s=1) first, then x^2 (s=0) with splits derived from x-hi.
__global__ __launch_bounds__(256, 2)
void phase1_kernel(const float* __restrict__ x, float* __restrict__ sa) {
    extern __shared__ char smem[];
    __shared__ float cst[64];
    const uint32_t sb = smem_u32(smem);
    const int tid = threadIdx.x;
    const int w = tid >> 5, lane = tid & 31;
    const int g = lane >> 2, q = lane & 3;
    const int n0w = w << 5;
    const int b  = blockIdx.y;
    const int n0 = blockIdx.x << 8;
    const float* xb = x + (size_t)b * Cq * Nq + n0;
    if (tid < 64) cst[tid] = gCst[tid];

    float acc[2][8][4];
#pragma unroll
    for (int i = 0; i < 2; ++i)
#pragma unroll
        for (int j = 0; j < 8; ++j)
#pragma unroll
            for (int e = 0; e < 4; ++e) acc[i][j][e] = 0.f;

    auto fill = [&](int ch) {
        const uint32_t base = sb + (uint32_t)(ch % 3) * P1_BUF;
        const float* xc = xb + (size_t)(ch << 4) * Nq;
        // A: 16 rows(c) x 256n, row pitch 1040B
#pragma unroll
        for (int it = 0; it < 4; ++it) {
            int u = tid + (it << 8);
            int row = u >> 6, seg = u & 63;
            CP16(base + (uint32_t)row * 1040u + (uint32_t)(seg << 4),
                 xc + (size_t)row * Nq + (seg << 2));
        }
        // B: fp16 image, 512 uint4
#pragma unroll
        for (int it = 0; it < 2; ++it) {
            int u = tid + (it << 8);
            CP16(base + P1_BOFF + (uint32_t)(u << 4), &gW16[ch][u]);
        }
        CPCOMMIT();
    };

    auto gemm = [&](int buf) {
        const float* fA = (const float*)(smem + (uint32_t)buf * P1_BUF);
        const uint4* fB = (const uint4*)(smem + (uint32_t)buf * P1_BUF + P1_BOFF);
        float xv[2][8];
#pragma unroll
        for (int i = 0; i < 2; ++i) {
            const float* pa = fA + n0w + (i << 4) + g;
            xv[i][0] = pa[(2 * q) * 260];         xv[i][1] = pa[(2 * q + 1) * 260];
            xv[i][2] = pa[(2 * q + 8) * 260];     xv[i][3] = pa[(2 * q + 9) * 260];
            xv[i][4] = pa[(2 * q) * 260 + 8];     xv[i][5] = pa[(2 * q + 1) * 260 + 8];
            xv[i][6] = pa[(2 * q + 8) * 260 + 8]; xv[i][7] = pa[(2 * q + 9) * 260 + 8];
        }
        // x splits (used by s=1 passes, and to derive x^2 splits)
        unsigned xH[2][4], xL[2][4];
#pragma unroll
        for (int i = 0; i < 2; ++i) {
            splitpair(xv[i][0], xv[i][1], xH[i][0], xL[i][0]);   // row r,   slots 2q,2q+1
            splitpair(xv[i][4], xv[i][5], xH[i][1], xL[i][1]);   // row r+8
            splitpair(xv[i][2], xv[i][3], xH[i][2], xL[i][2]);   // row r,   slots 2q+8,2q+9
            splitpair(xv[i][6], xv[i][7], xH[i][3], xL[i][3]);   // row r+8
        }
        // ---- s=1 passes: x against w2 image ----
#pragma unroll
        for (int jb = 0; jb < 2; ++jb) {
            uint4 w4[4];
#pragma unroll
            for (int jj = 0; jj < 4; ++jj)
                w4[jj] = fB[(((8 + (jb << 2) + jj) * 8 + g) << 2) + q];
#pragma unroll
            for (int jj = 0; jj < 4; ++jj) {
                unsigned bh[2] = { w4[jj].x, w4[jj].y };
                mmaH(acc[0][(jb << 2) + jj], xH[0], bh);
                mmaH(acc[1][(jb << 2) + jj], xH[1], bh);
            }
#pragma unroll
            for (int jj = 0; jj < 4; ++jj) {
                unsigned bl[2] = { w4[jj].z, w4[jj].w };
                mmaH(acc[0][(jb << 2) + jj], xH[0], bl);
                mmaH(acc[1][(jb << 2) + jj], xH[1], bl);
            }
#pragma unroll
            for (int jj = 0; jj < 4; ++jj) {
                unsigned bh[2] = { w4[jj].x, w4[jj].y };
                mmaH(acc[0][(jb << 2) + jj], xL[0], bh);
                mmaH(acc[1][(jb << 2) + jj], xL[1], bh);
            }
        }
        // x^2 splits from x-hi: qh = hmul2(xh,xh); ql = fp16(x*x - float(qh))
        unsigned qH[2][4], qL[2][4];
#pragma unroll
        for (int i = 0; i < 2; ++i) {
            // fragment r: reg order 0:(xv0,xv1) 1:(xv4,xv5) 2:(xv2,xv3) 3:(xv6,xv7)
            const int vi[4][2] = { {0,1}, {4,5}, {2,3}, {6,7} };
#pragma unroll
            for (int r = 0; r < 4; ++r) {
                unsigned qh = hmul2(xH[i][r], xH[i][r]);
                float2 f = unpk2h(qh);
                float a0 = xv[i][vi[r][0]], a1 = xv[i][vi[r][1]];
                qH[i][r] = qh;
                qL[i][r] = pk2h(fmaf(a0, a0, -f.x), fmaf(a1, a1, -f.y));
            }
        }
        // ---- s=0 passes: x^2 against w1 image ----
#pragma unroll
        for (int jb = 0; jb < 2; ++jb) {
            uint4 w4[4];
#pragma unroll
            for (int jj = 0; jj < 4; ++jj)
                w4[jj] = fB[((((jb << 2) + jj) * 8 + g) << 2) + q];
#pragma unroll
            for (int jj = 0; jj < 4; ++jj) {
                unsigned bh[2] = { w4[jj].x, w4[jj].y };
                mmaH(acc[0][(jb << 2) + jj], qH[0], bh);
                mmaH(acc[1][(jb << 2) + jj], qH[1], bh);
            }
#pragma unroll
            for (int jj = 0; jj < 4; ++jj) {
                unsigned bl[2] = { w4[jj].z, w4[jj].w };
                mmaH(acc[0][(jb << 2) + jj], qH[0], bl);
                mmaH(acc[1][(jb << 2) + jj], qH[1], bl);
            }
#pragma unroll
            for (int jj = 0; jj < 4; ++jj) {
                unsigned bh[2] = { w4[jj].x, w4[jj].y };
                mmaH(acc[0][(jb << 2) + jj], qL[0], bh);
                mmaH(acc[1][(jb << 2) + jj], qL[1], bh);
            }
        }
    };

    fill(0); fill(1);
    for (int ch = 0; ch < 32; ++ch) {
        if (ch < 31) { CPWAIT1(); } else { CPWAIT0(); }
        __syncthreads();
        if (ch + 2 < 32) fill(ch + 2);
        gemm(ch % 3);
    }
    CPWAIT0();
    __syncthreads();

    // stage d2 in smem (overlays buffers)
    float* d2 = (float*)smem;
#pragma unroll
    for (int i = 0; i < 2; ++i) {
        int r0 = n0w + (i << 4) + g;
#pragma unroll
        for (int j = 0; j < 8; ++j) {
            int kc = (j << 3) + (q << 1);
            *(float2*)&d2[r0 * 66 + kc]       = make_float2(acc[i][j][0], acc[i][j][1]);
            *(float2*)&d2[(r0 + 8) * 66 + kc] = make_float2(acc[i][j][2], acc[i][j][3]);
        }
    }
    __syncthreads();

    // softmax: one thread per n
    {
        float e[64];
#pragma unroll
        for (int k = 0; k < 64; ++k) e[k] = d2[tid * 66 + k] + cst[k];
        float mn = e[0];
#pragma unroll
        for (int k = 1; k < 64; ++k) mn = fminf(mn, e[k]);
        float s = 0.f;
#pragma unroll
        for (int k = 0; k < 64; ++k) {
            float t = __expf(-0.5f * (e[k] - mn));
            e[k] = t;
            s += t;
        }
        float r = 1.f / s;
        float* sp = sa + (size_t)b * Kq * Nq + n0 + tid;
#pragma unroll
        for (int k = 0; k < 64; ++k) sp[(size_t)k * Nq] = e[k] * r;
    }
}

// ====== fused w_sum + scale + fp16 split-convert (single pass over sa) ======
__global__ void wsum_sa16_kernel(const float* __restrict__ sa) {
    const int bk = blockIdx.x;      // 1024
    const int tid = threadIdx.x;    // 256, one 16n chunk each
    const float4* src = (const float4*)(sa + (size_t)bk * Nq + (size_t)tid * 16);
    float v[16];
    float s = 0.f, m = 0.f;
#pragma unroll
    for (int i = 0; i < 4; ++i) {
        float4 a = src[i];
        v[4 * i + 0] = a.x; v[4 * i + 1] = a.y;
        v[4 * i + 2] = a.z; v[4 * i + 3] = a.w;
        s += (a.x + a.y) + (a.z + a.w);
        m = fmaxf(m, fmaxf(fmaxf(a.x, a.y), fmaxf(a.z, a.w)));
    }
#pragma unroll
    for (int off = 16; off; off >>= 1) {
        s += __shfl_xor_sync(0xffffffffu, s, off);
        m = fmaxf(m, __shfl_xor_sync(0xffffffffu, m, off));
    }
    __shared__ float red[8], redm[8];
    __shared__ float sfk;
    if ((tid & 31) == 0) { red[tid >> 5] = s; redm[tid >> 5] = m; }
    __syncthreads();
    if (tid == 0) {
        float t = 0.f, mm = 0.f;
#pragma unroll
        for (int i = 0; i < 8; ++i) { t += red[i]; mm = fmaxf(mm, redm[i]); }
        g_wsum[bk >> 6][bk & 63] = t;
        int e = (mm > 0.f) ? ilogbf(mm) : 0;
        sfk = exp2f((float)(-e));
        g_invf[bk] = exp2f((float)(e));
    }
    __syncthreads();
    const float f = sfk;
    uint4* dst = &g_sa16[((size_t)bk * 256 + tid) * 4];
#pragma unroll
    for (int qq = 0; qq < 4; ++qq) {
        unsigned h0, l0, h1, l1;
        splitpair(v[2 * qq] * f,     v[2 * qq + 1] * f, h0, l0);
        splitpair(v[2 * qq + 8] * f, v[2 * qq + 9] * f, h1, l1);
        uint4 o; o.x = h0; o.y = h1; o.z = l0; o.w = l1;
        dst[qq] = o;
    }
}

// ================= phase 2: wx[c,k] = sum_n x[c,n]*sa[k,n] (3xFP16 mma) =================
// grid (2 ctile, 16 b, 8 seg). block tile 256c x 64k, 32 chunks of 16 n (1 k16 step).
__global__ __launch_bounds__(256, 2)
void phase2_kernel(const float* __restrict__ x, const float* __restrict__ dummy) {
    extern __shared__ char smem[];
    const uint32_t sb = smem_u32(smem);
    const int tid = threadIdx.x;
    const int w = tid >> 5, lane = tid & 31;
    const int g = lane >> 2, q = lane & 3;
    const int c0w = w << 5;
    const int c0 = (int)blockIdx.x << 8;
    const int b  = blockIdx.y;
    const int seg = blockIdx.z;
    const int n0 = seg << 9;
    const float* xb = x + ((size_t)b * Cq + c0) * Nq + n0;

    float acc[2][8][4];
#pragma unroll
    for (int i = 0; i < 2; ++i)
#pragma unroll
        for (int j = 0; j < 8; ++j)
#pragma unroll
            for (int e = 0; e < 4; ++e) acc[i][j][e] = 0.f;

    auto fill = [&](int ch) {
        const uint32_t base = sb + (uint32_t)(ch % 3) * P2_BUF;
        const int nn = ch << 4;
        // A: 256 rows(c) x 16n, 64B rows with 16B-seg XOR swizzle
#pragma unroll
        for (int it = 0; it < 4; ++it) {
            int u = tid + (it << 8);
            int row = u >> 2, sg2 = u & 3;
            CP16(base + (uint32_t)(row << 6) + (uint32_t)((sg2 ^ ((row >> 1) & 3)) << 4),
                 xb + (size_t)row * Nq + nn + (sg2 << 2));
        }
        // B: pre-split sa16, 256 x 16B
        {
            int node = tid >> 2, qq = tid & 3;
            CP16(base + P2_BOFF + (uint32_t)(tid << 4),
                 &g_sa16[(((size_t)(b * 64 + node)) * 256 + (size_t)(seg * 32 + ch)) * 4 + qq]);
        }
        CPCOMMIT();
    };

    auto gemm = [&](int buf) {
        const float* fA = (const float*)(smem + (uint32_t)buf * P2_BUF);
        const uint4* fB = (const uint4*)(smem + (uint32_t)buf * P2_BUF + P2_BOFF);
        unsigned aH[2][4], aL[2][4];
#pragma unroll
        for (int i = 0; i < 2; ++i) {
            int r0 = c0w + (i << 4) + g;
            int r1 = r0 + 8;
            int k0 = ((r0 >> 1) & 3) << 2;
            int k1 = ((r1 >> 1) & 3) << 2;
            float2 p00 = *(const float2*)(fA + (r0 << 4) + ((2 * q) ^ k0));
            float2 p01 = *(const float2*)(fA + (r0 << 4) + ((2 * q + 8) ^ k0));
            float2 p10 = *(const float2*)(fA + (r1 << 4) + ((2 * q) ^ k1));
            float2 p11 = *(const float2*)(fA + (r1 << 4) + ((2 * q + 8) ^ k1));
            splitpair(p00.x, p00.y, aH[i][0], aL[i][0]);
            splitpair(p10.x, p10.y, aH[i][1], aL[i][1]);
            splitpair(p01.x, p01.y, aH[i][2], aL[i][2]);
            splitpair(p11.x, p11.y, aH[i][3], aL[i][3]);
        }
#pragma unroll
        for (int jb = 0; jb < 2; ++jb) {
            uint4 w4[4];
#pragma unroll
            for (int jj = 0; jj < 4; ++jj)
                w4[jj] = fB[(((((jb << 2) + jj) << 3) + g) << 2) + q];
#pragma unroll
            for (int jj = 0; jj < 4; ++jj) {
                unsigned bh[2] = { w4[jj].x, w4[jj].y };
                mmaH(acc[0][(jb << 2) + jj], aH[0], bh);
                mmaH(acc[1][(jb << 2) + jj], aH[1], bh);
            }
#pragma unroll
            for (int jj = 0; jj < 4; ++jj) {
                unsigned bl[2] = { w4[jj].z, w4[jj].w };
                mmaH(acc[0][(jb << 2) + jj], aH[0], bl);
                mmaH(acc[1][(jb << 2) + jj], aH[1], bl);
            }
#pragma unroll
            for (int jj = 0; jj < 4; ++jj) {
                unsigned bh[2] = { w4[jj].x, w4[jj].y };
                mmaH(acc[0][(jb << 2) + jj], aL[0], bh);
                mmaH(acc[1][(jb << 2) + jj], aL[1], bh);
            }
        }
    };

    fill(0); fill(1);
    for (int ch = 0; ch < 32; ++ch) {
        if (ch < 31) { CPWAIT1(); } else { CPWAIT0(); }
        __syncthreads();
        if (ch + 2 < 32) fill(ch + 2);
        gemm(ch % 3);
    }

    // epilogue: unscale by exact power-of-2 invf, scatter D[c,k] partials
    float* basep = &g_wx8[seg][b][0][0];
#pragma unroll
    for (int j = 0; j < 8; ++j) {
        int kc = (j << 3) + (q << 1);
        float f0 = g_invf[b * 64 + kc];
        float f1 = g_invf[b * 64 + kc + 1];
#pragma unroll
        for (int i = 0; i < 2; ++i) {
            int cc = c0 + c0w + (i << 4) + g;
            basep[(size_t)kc * Cq + cc]           = acc[i][j][0] * f0;
            basep[(size_t)(kc + 1) * Cq + cc]     = acc[i][j][1] * f1;
            basep[(size_t)kc * Cq + cc + 8]       = acc[i][j][2] * f0;
            basep[(size_t)(kc + 1) * Cq + cc + 8] = acc[i][j][3] * f1;
        }
    }
}

// ================= phase 3: nodes + per-row l2norm =================
__global__ void phase3_kernel(const float* __restrict__ anchor) {
    const int bk = blockIdx.x;     // 1024
    const int b = bk >> 6, k = bk & 63;
    const int tid = threadIdx.x;   // 128
    const float wsv = g_wsum[b][k];
    const float invw = 1.f / (wsv + 1e-9f);
    float t[4];
    float ssq = 0.f;
#pragma unroll
    for (int j = 0; j < 4; ++j) {
        int c = tid + j * 128;
        float wx = 0.f;
#pragma unroll
        for (int s = 0; s < 8; ++s) wx += g_wx8[s][b][k][c];
        float nd = (wx - wsv * anchor[k * Cq + c]) * gInvS[k][c] * invw;
        t[j] = nd;
        ssq += nd * nd;
    }
#pragma unroll
    for (int off = 16; off; off >>= 1) ssq += __shfl_xor_sync(0xffffffffu, ssq, off);
    __shared__ float red[4];
    __shared__ float totsh;
    if ((tid & 31) == 0) red[tid >> 5] = ssq;
    __syncthreads();
    if (tid == 0) totsh = red[0] + red[1] + red[2] + red[3];
    __syncthreads();
    float total = totsh;
    float scale = 1.f / fmaxf(sqrtf(total), 1e-12f);
#pragma unroll
    for (int j = 0; j < 4; ++j) {
        int c = tid + j * 128;
        g_nodes[b][k][c] = t[j] * scale;
    }
    if (tid == 0) g_row[b][k] = total * scale * scale;
}

// ================= phase 4: global l2norm + output =================
__global__ void phase4_kernel(float* __restrict__ outflat) {
    const int b = blockIdx.x;      // 16
    const int tid = threadIdx.x;   // 256
    __shared__ float red[64];
    __shared__ float gsh;
    if (tid < 64) red[tid] = g_row[b][tid];
    __syncthreads();
    if (tid == 0) {
        float s = 0.f;
#pragma unroll
        for (int i = 0; i < 64; ++i) s += red[i];
        gsh = 1.f / fmaxf(sqrtf(s), 1e-12f);
    }
    __syncthreads();
    float g = gsh;
    const float* np = &g_nodes[b][0][0];
    float* op = outflat + (size_t)b * Kq * Cq;
    for (int i = tid; i < Kq * Cq; i += 256) op[i] = np[i] * g;
}

// ================= launch =================
extern "C" void kernel_launch(void* const* d_in, const int* in_sizes, int n_in,
                              void* d_out, int out_size) {
    const float* x      = (const float*)d_in[0];
    const float* anchor = (const float*)d_in[1];
    const float* sraw   = (const float*)d_in[2];
    float* outf = (float*)d_out;

    const int FLAT = Bq * Cq * Kq;      // 524288
    const int SA   = Bq * Kq * Nq;      // 4194304

    float* sa_dev = nullptr;
    cudaGetSymbolAddress((void**)&sa_dev, g_sa);
    float* nodes_dev = nullptr;
    cudaGetSymbolAddress((void**)&nodes_dev, g_nodes);

    float* sa_ptr;
    float* flat_ptr;
    if (out_size == FLAT) {
        flat_ptr = outf;
        sa_ptr = sa_dev;
    } else if (out_size == SA) {
        sa_ptr = outf;
        flat_ptr = nodes_dev;
    } else {
        flat_ptr = outf;
        sa_ptr = outf + FLAT;
    }

    static bool attr_done = false;
    if (!attr_done) {
        cudaFuncSetAttribute(phase1_kernel,
                             cudaFuncAttributeMaxDynamicSharedMemorySize, P1_SMEM);
        cudaFuncSetAttribute(phase2_kernel,
                             cudaFuncAttributeMaxDynamicSharedMemorySize, P2_SMEM);
        attr_done = true;
    }

    prep_kernel<<<Kq, 256>>>(anchor, sraw);
    phase1_kernel<<<dim3(Nq / 256, Bq), 256, P1_SMEM>>>(x, sa_ptr);
    wsum_sa16_kernel<<<Bq * Kq, 256>>>(sa_ptr);
    phase2_kernel<<<dim3(Cq / 256, Bq, 8), 256, P2_SMEM>>>(x, nullptr);
    phase3_kernel<<<Bq * Kq, 128>>>(anchor);
    phase4_kernel<<<Bq, 256>>>(flat_ptr);
}

// round 13
// speedup vs baseline: 1.1232x; 1.1232x over previous
#include <cuda_runtime.h>
#include <cstdint>

#define Bq 16
#define Cq 512
#define Nq 4096
#define Kq 64

// ================= scratch (static device allocations only) =================
__device__ uint4 gW16[32][512];            // per-16c-chunk fp16 W images (8KB each)
__device__ float gInvS[Kq][Cq];
__device__ float gCst[Kq];
__device__ float g_sa[(size_t)Bq*Kq*Nq];
__device__ uint2 g_sa16b[(size_t)Bq*Kq*256*4]; // hi-only fp16 sa image (8.4MB)
__device__ float g_wsp[Bq][16][Kq];            // per-(b,ntile) wsum partials
__device__ float g_wx8[8][Bq][Kq][Cq];
__device__ float g_row[Bq][Kq];
__device__ float g_nodes[Bq][Kq][Cq];

#define SA_SCALE   2048.0f
#define SA_INV     4.8828125e-4f   // 2^-11

// ================= helpers =================
__device__ __forceinline__ unsigned pk2h(float lo, float hi) {
    unsigned d;
    asm("cvt.rn.f16x2.f32 %0, %1, %2;" : "=r"(d) : "f"(hi), "f"(lo));
    return d;
}
__device__ __forceinline__ float2 unpk2h(unsigned u) {
    float lo, hi;
    asm("{.reg .f16 a,b; mov.b32 {a,b}, %2; cvt.f32.f16 %0, a; cvt.f32.f16 %1, b;}"
        : "=f"(lo), "=f"(hi) : "r"(u));
    return make_float2(lo, hi);
}
// split pair (v0=even slot, v1=odd slot) into fp16x2 hi and lo regs
__device__ __forceinline__ void splitpair(float v0, float v1, unsigned& h, unsigned& l) {
    h = pk2h(v0, v1);
    float2 f = unpk2h(h);
    l = pk2h(v0 - f.x, v1 - f.y);
}
__device__ __forceinline__ void mmaH(float* d, const unsigned* a, const unsigned* b) {
    asm volatile(
        "mma.sync.aligned.m16n8k16.row.col.f32.f16.f16.f32 "
        "{%0,%1,%2,%3}, {%4,%5,%6,%7}, {%8,%9}, {%0,%1,%2,%3};"
        : "+f"(d[0]), "+f"(d[1]), "+f"(d[2]), "+f"(d[3])
        : "r"(a[0]), "r"(a[1]), "r"(a[2]), "r"(a[3]), "r"(b[0]), "r"(b[1]));
}
__device__ __forceinline__ uint32_t smem_u32(const void* p) {
    uint32_t a;
    asm("{ .reg .u64 t; cvta.to.shared.u64 t, %1; cvt.u32.u64 %0, t; }" : "=r"(a) : "l"(p));
    return a;
}
#define CP16(dst, src) asm volatile("cp.async.cg.shared.global [%0], [%1], 16;" :: "r"(dst), "l"(src))
#define CPCOMMIT()     asm volatile("cp.async.commit_group;" ::: "memory")
#define CPWAIT1()      asm volatile("cp.async.wait_group 1;" ::: "memory")
#define CPWAIT0()      asm volatile("cp.async.wait_group 0;" ::: "memory")

// ===== phase1: 3 bufs of { A raw x [16c][260f pitch], B fp16 image 8KB } =====
#define P1_BUF   24832u
#define P1_BOFF  16640u
#define P1_SMEM  74496
// ===== phase2: 3 bufs of { A raw x [256c][16n] swizzled 16KB, B hi sa16 2KB } =====
#define P2_BUF   18432u
#define P2_BOFF  16384u
#define P2_SMEM  55296

// ================= prep: sigma, fp16 W images, const =================
__global__ void prep_kernel(const float* __restrict__ anchor,
                            const float* __restrict__ sraw) {
    const int k = blockIdx.x;       // 64
    const int tid = threadIdx.x;    // 256
    float part = 0.f;
#pragma unroll
    for (int jj = 0; jj < 2; ++jj) {
        int c = tid + jj * 256;
        float sr = sraw[k * Cq + c];
        float sg = 1.f / (1.f + __expf(-sr));
        float a  = anchor[k * Cq + c];
        float i2 = 1.f / (sg * sg);
        float w2 = -2.f * a * i2;
        gInvS[k][c] = 1.f / sg;
        part += a * a * i2;
        int ch = c >> 4, cl = c & 15;
        int j = k >> 3, gg = k & 7;
        int q = (cl >> 1) & 3, reg = cl >> 3, half = cl & 1;
        float vals[2] = { i2, w2 };   // step0 = x^2 weight, step1 = x weight
#pragma unroll
        for (int s = 0; s < 2; ++s) {
            unsigned hp, lp;
            splitpair(vals[s], 0.f, hp, lp);
            unsigned short* base =
                (unsigned short*)&gW16[ch][(((s * 8 + j) * 8 + gg) * 4 + q)];
            base[reg * 2 + half]     = (unsigned short)(hp & 0xFFFFu);
            base[4 + reg * 2 + half] = (unsigned short)(lp & 0xFFFFu);
        }
    }
#pragma unroll
    for (int off = 16; off; off >>= 1) part += __shfl_xor_sync(0xffffffffu, part, off);
    __shared__ float red[8];
    if ((tid & 31) == 0) red[tid >> 5] = part;
    __syncthreads();
    if (tid == 0) {
        float s = 0.f;
#pragma unroll
        for (int i = 0; i < 8; ++i) s += red[i];
        gCst[k] = s;
    }
}

// ================= phase 1: distance GEMM (3xFP16 mma, R11 order) + softmax
//                   + fused sa16/wsum emission =================
__global__ __launch_bounds__(256, 2)
void phase1_kernel(const float* __restrict__ x, float* __restrict__ sa) {
    extern __shared__ char smem[];
    __shared__ float cst[64];
    const uint32_t sb = smem_u32(smem);
    const int tid = threadIdx.x;
    const int w = tid >> 5, lane = tid & 31;
    const int g = lane >> 2, q = lane & 3;
    const int n0w = w << 5;
    const int b  = blockIdx.y;
    const int ntile = blockIdx.x;
    const int n0 = ntile << 8;
    const float* xb = x + (size_t)b * Cq * Nq + n0;
    if (tid < 64) cst[tid] = gCst[tid];

    float acc[2][8][4];
#pragma unroll
    for (int i = 0; i < 2; ++i)
#pragma unroll
        for (int j = 0; j < 8; ++j)
#pragma unroll
            for (int e = 0; e < 4; ++e) acc[i][j][e] = 0.f;

    auto fill = [&](int ch) {
        const uint32_t base = sb + (uint32_t)(ch % 3) * P1_BUF;
        const float* xc = xb + (size_t)(ch << 4) * Nq;
#pragma unroll
        for (int it = 0; it < 4; ++it) {
            int u = tid + (it << 8);
            int row = u >> 6, seg = u & 63;
            CP16(base + (uint32_t)row * 1040u + (uint32_t)(seg << 4),
                 xc + (size_t)row * Nq + (seg << 2));
        }
#pragma unroll
        for (int it = 0; it < 2; ++it) {
            int u = tid + (it << 8);
            CP16(base + P1_BOFF + (uint32_t)(u << 4), &gW16[ch][u]);
        }
        CPCOMMIT();
    };

    // R11-form gemm: per s-step split (squares in f32), passes hh/hl/lh per jb
    auto gemm = [&](int buf) {
        const float* fA = (const float*)(smem + (uint32_t)buf * P1_BUF);
        const uint4* fB = (const uint4*)(smem + (uint32_t)buf * P1_BUF + P1_BOFF);
        float xv[2][8];
#pragma unroll
        for (int i = 0; i < 2; ++i) {
            const float* pa = fA + n0w + (i << 4) + g;
            xv[i][0] = pa[(2 * q) * 260];         xv[i][1] = pa[(2 * q + 1) * 260];
            xv[i][2] = pa[(2 * q + 8) * 260];     xv[i][3] = pa[(2 * q + 9) * 260];
            xv[i][4] = pa[(2 * q) * 260 + 8];     xv[i][5] = pa[(2 * q + 1) * 260 + 8];
            xv[i][6] = pa[(2 * q + 8) * 260 + 8]; xv[i][7] = pa[(2 * q + 9) * 260 + 8];
        }
#pragma unroll
        for (int s = 0; s < 2; ++s) {
            unsigned aH[2][4], aL[2][4];
#pragma unroll
            for (int i = 0; i < 2; ++i) {
                float e0, e1, e2, e3, e4, e5, e6, e7;
                if (s == 0) {
                    e0 = xv[i][0] * xv[i][0]; e1 = xv[i][1] * xv[i][1];
                    e2 = xv[i][2] * xv[i][2]; e3 = xv[i][3] * xv[i][3];
                    e4 = xv[i][4] * xv[i][4]; e5 = xv[i][5] * xv[i][5];
                    e6 = xv[i][6] * xv[i][6]; e7 = xv[i][7] * xv[i][7];
                } else {
                    e0 = xv[i][0]; e1 = xv[i][1]; e2 = xv[i][2]; e3 = xv[i][3];
                    e4 = xv[i][4]; e5 = xv[i][5]; e6 = xv[i][6]; e7 = xv[i][7];
                }
                splitpair(e0, e1, aH[i][0], aL[i][0]);
                splitpair(e4, e5, aH[i][1], aL[i][1]);
                splitpair(e2, e3, aH[i][2], aL[i][2]);
                splitpair(e6, e7, aH[i][3], aL[i][3]);
            }
#pragma unroll
            for (int jb = 0; jb < 2; ++jb) {
                uint4 w4[4];
#pragma unroll
                for (int jj = 0; jj < 4; ++jj)
                    w4[jj] = fB[(((s * 8 + (jb << 2) + jj) * 8 + g) << 2) + q];
#pragma unroll
                for (int jj = 0; jj < 4; ++jj) {
                    unsigned bh[2] = { w4[jj].x, w4[jj].y };
                    mmaH(acc[0][(jb << 2) + jj], aH[0], bh);
                    mmaH(acc[1][(jb << 2) + jj], aH[1], bh);
                }
#pragma unroll
                for (int jj = 0; jj < 4; ++jj) {
                    unsigned bl[2] = { w4[jj].z, w4[jj].w };
                    mmaH(acc[0][(jb << 2) + jj], aH[0], bl);
                    mmaH(acc[1][(jb << 2) + jj], aH[1], bl);
                }
#pragma unroll
                for (int jj = 0; jj < 4; ++jj) {
                    unsigned bh[2] = { w4[jj].x, w4[jj].y };
                    mmaH(acc[0][(jb << 2) + jj], aL[0], bh);
                    mmaH(acc[1][(jb << 2) + jj], aL[1], bh);
                }
            }
        }
    };

    fill(0); fill(1);
    for (int ch = 0; ch < 32; ++ch) {
        if (ch < 31) { CPWAIT1(); } else { CPWAIT0(); }
        __syncthreads();
        if (ch + 2 < 32) fill(ch + 2);
        gemm(ch % 3);
    }
    CPWAIT0();
    __syncthreads();

    // stage d2 in smem (overlays buffers)
    float* d2 = (float*)smem;
#pragma unroll
    for (int i = 0; i < 2; ++i) {
        int r0 = n0w + (i << 4) + g;
#pragma unroll
        for (int j = 0; j < 8; ++j) {
            int kc = (j << 3) + (q << 1);
            *(float2*)&d2[r0 * 66 + kc]       = make_float2(acc[i][j][0], acc[i][j][1]);
            *(float2*)&d2[(r0 + 8) * 66 + kc] = make_float2(acc[i][j][2], acc[i][j][3]);
        }
    }
    __syncthreads();

    // softmax: one thread per n (p values kept in e[])
    float e[64];
    {
#pragma unroll
        for (int k = 0; k < 64; ++k) e[k] = d2[tid * 66 + k] + cst[k];
        float mn = e[0];
#pragma unroll
        for (int k = 1; k < 64; ++k) mn = fminf(mn, e[k]);
        float s = 0.f;
#pragma unroll
        for (int k = 0; k < 64; ++k) {
            float t = __expf(-0.5f * (e[k] - mn));
            e[k] = t;
            s += t;
        }
        float r = 1.f / s;
#pragma unroll
        for (int k = 0; k < 64; ++k) e[k] *= r;
    }
    __syncthreads();   // all d2 reads done before overwrite

    // transpose p into [k][256] (pitch 264), write sa fp32
    float* psh = (float*)smem;
#pragma unroll
    for (int k = 0; k < 64; ++k) psh[k * 264 + tid] = e[k];
    {
        float* sp = sa + (size_t)b * Kq * Nq + n0 + tid;
#pragma unroll
        for (int k = 0; k < 64; ++k) sp[(size_t)k * Nq] = e[k];
    }
    __syncthreads();

    // build hi-only fp16 sa image + wsum partials. unit u = (k, ch16)
    float* wssh = (float*)(smem + 67584);
#pragma unroll
    for (int it = 0; it < 4; ++it) {
        int u = tid + (it << 8);
        int k = u >> 4, ch = u & 15;
        const float* src = psh + k * 264 + (ch << 4);
        float4 v0 = *(const float4*)(src);
        float4 v1 = *(const float4*)(src + 4);
        float4 v2 = *(const float4*)(src + 8);
        float4 v3 = *(const float4*)(src + 12);
        uint4 oA, oB;
        oA.x = pk2h(v0.x * SA_SCALE, v0.y * SA_SCALE);
        oA.y = pk2h(v2.x * SA_SCALE, v2.y * SA_SCALE);
        oA.z = pk2h(v0.z * SA_SCALE, v0.w * SA_SCALE);
        oA.w = pk2h(v2.z * SA_SCALE, v2.w * SA_SCALE);
        oB.x = pk2h(v1.x * SA_SCALE, v1.y * SA_SCALE);
        oB.y = pk2h(v3.x * SA_SCALE, v3.y * SA_SCALE);
        oB.z = pk2h(v1.z * SA_SCALE, v1.w * SA_SCALE);
        oB.w = pk2h(v3.z * SA_SCALE, v3.w * SA_SCALE);
        size_t dstbase = ((size_t)((b * 64 + k) * 256 + (ntile << 4) + ch)) << 2;
        *(uint4*)&g_sa16b[dstbase]     = oA;   // qq 0,1
        *(uint4*)&g_sa16b[dstbase + 2] = oB;   // qq 2,3
        float sA = ((v0.x + v0.y) + (v0.z + v0.w)) + ((v1.x + v1.y) + (v1.z + v1.w));
        float sB = ((v2.x + v2.y) + (v2.z + v2.w)) + ((v3.x + v3.y) + (v3.z + v3.w));
        wssh[u] = sA + sB;
    }
    __syncthreads();
    if (tid < 64) {
        float s = 0.f;
#pragma unroll
        for (int c = 0; c < 16; ++c) s += wssh[tid * 16 + c];
        g_wsp[b][ntile][tid] = s;
    }
}

// ================= phase 2: wx[c,k] = sum_n x[c,n]*sa16[k,n]  (2-pass fp16) =====
// grid (2 ctile, 16 b, 8 seg). block tile 256c x 64k, 32 chunks of 16 n.
__global__ __launch_bounds__(256, 2)
void phase2_kernel(const float* __restrict__ x) {
    extern __shared__ char smem[];
    const uint32_t sb = smem_u32(smem);
    const int tid = threadIdx.x;
    const int w = tid >> 5, lane = tid & 31;
    const int g = lane >> 2, q = lane & 3;
    const int c0w = w << 5;
    const int c0 = (int)blockIdx.x << 8;
    const int b  = blockIdx.y;
    const int seg = blockIdx.z;
    const int n0 = seg << 9;
    const float* xb = x + ((size_t)b * Cq + c0) * Nq + n0;

    float acc[2][8][4];
#pragma unroll
    for (int i = 0; i < 2; ++i)
#pragma unroll
        for (int j = 0; j < 8; ++j)
#pragma unroll
            for (int e = 0; e < 4; ++e) acc[i][j][e] = 0.f;

    auto fill = [&](int ch) {
        const uint32_t base = sb + (uint32_t)(ch % 3) * P2_BUF;
        const int nn = ch << 4;
        // A: 256 rows(c) x 16n, 64B rows with 16B-seg XOR swizzle
#pragma unroll
        for (int it = 0; it < 4; ++it) {
            int u = tid + (it << 8);
            int row = u >> 2, sg2 = u & 3;
            CP16(base + (uint32_t)(row << 6) + (uint32_t)((sg2 ^ ((row >> 1) & 3)) << 4),
                 xb + (size_t)row * Nq + nn + (sg2 << 2));
        }
        // B: hi-only sa16, 128 x 16B
        if (tid < 128) {
            int node = tid >> 1, qq2 = tid & 1;
            CP16(base + P2_BOFF + (uint32_t)(tid << 4),
                 &g_sa16b[(((size_t)((b * 64 + node) * 256 + (seg << 5) + ch)) << 2) + (qq2 << 1)]);
        }
        CPCOMMIT();
    };

    auto gemm = [&](int buf) {
        const float* fA = (const float*)(smem + (uint32_t)buf * P2_BUF);
        const uint2* fB = (const uint2*)(smem + (uint32_t)buf * P2_BUF + P2_BOFF);
        unsigned aH[2][4], aL[2][4];
#pragma unroll
        for (int i = 0; i < 2; ++i) {
            int r0 = c0w + (i << 4) + g;
            int r1 = r0 + 8;
            int k0 = ((r0 >> 1) & 3) << 2;
            int k1 = ((r1 >> 1) & 3) << 2;
            float2 p00 = *(const float2*)(fA + (r0 << 4) + ((2 * q) ^ k0));
            float2 p01 = *(const float2*)(fA + (r0 << 4) + ((2 * q + 8) ^ k0));
            float2 p10 = *(const float2*)(fA + (r1 << 4) + ((2 * q) ^ k1));
            float2 p11 = *(const float2*)(fA + (r1 << 4) + ((2 * q + 8) ^ k1));
            splitpair(p00.x, p00.y, aH[i][0], aL[i][0]);
            splitpair(p10.x, p10.y, aH[i][1], aL[i][1]);
            splitpair(p01.x, p01.y, aH[i][2], aL[i][2]);
            splitpair(p11.x, p11.y, aH[i][3], aL[i][3]);
        }
#pragma unroll
        for (int jb = 0; jb < 2; ++jb) {
            uint2 w2[4];
#pragma unroll
            for (int jj = 0; jj < 4; ++jj)
                w2[jj] = fB[(((((jb << 2) + jj) << 3) + g) << 2) + q];
#pragma unroll
            for (int jj = 0; jj < 4; ++jj) {
                unsigned bh[2] = { w2[jj].x, w2[jj].y };
                mmaH(acc[0][(jb << 2) + jj], aH[0], bh);
                mmaH(acc[1][(jb << 2) + jj], aH[1], bh);
            }
#pragma unroll
            for (int jj = 0; jj < 4; ++jj) {
                unsigned bh[2] = { w2[jj].x, w2[jj].y };
                mmaH(acc[0][(jb << 2) + jj], aL[0], bh);
                mmaH(acc[1][(jb << 2) + jj], aL[1], bh);
            }
        }
    };

    fill(0); fill(1);
    for (int ch = 0; ch < 32; ++ch) {
        if (ch < 31) { CPWAIT1(); } else { CPWAIT0(); }
        __syncthreads();
        if (ch + 2 < 32) fill(ch + 2);
        gemm(ch % 3);
    }

    // epilogue: unscale by 2^-11, scatter D[c,k] partials
    float* basep = &g_wx8[seg][b][0][0];
#pragma unroll
    for (int j = 0; j < 8; ++j) {
        int kc = (j << 3) + (q << 1);
#pragma unroll
        for (int i = 0; i < 2; ++i) {
            int cc = c0 + c0w + (i << 4) + g;
            basep[(size_t)kc * Cq + cc]           = acc[i][j][0] * SA_INV;
            basep[(size_t)(kc + 1) * Cq + cc]     = acc[i][j][1] * SA_INV;
            basep[(size_t)kc * Cq + cc + 8]       = acc[i][j][2] * SA_INV;
            basep[(size_t)(kc + 1) * Cq + cc + 8] = acc[i][j][3] * SA_INV;
        }
    }
}

// ================= phase 3: nodes + per-row l2norm =================
__global__ void phase3_kernel(const float* __restrict__ anchor) {
    const int bk = blockIdx.x;     // 1024
    const int b = bk >> 6, k = bk & 63;
    const int tid = threadIdx.x;   // 128
    float wsv = 0.f;
#pragma unroll
    for (int t = 0; t < 16; ++t) wsv += g_wsp[b][t][k];
    const float invw = 1.f / (wsv + 1e-9f);
    float t4[4];
    float ssq = 0.f;
#pragma unroll
    for (int j = 0; j < 4; ++j) {
        int c = tid + j * 128;
        float wx = 0.f;
#pragma unroll
        for (int s = 0; s < 8; ++s) wx += g_wx8[s][b][k][c];
        float nd = (wx - wsv * anchor[k * Cq + c]) * gInvS[k][c] * invw;
        t4[j] = nd;
        ssq += nd * nd;
    }
#pragma unroll
    for (int off = 16; off; off >>= 1) ssq += __shfl_xor_sync(0xffffffffu, ssq, off);
    __shared__ float red[4];
    __shared__ float totsh;
    if ((tid & 31) == 0) red[tid >> 5] = ssq;
    __syncthreads();
    if (tid == 0) totsh = red[0] + red[1] + red[2] + red[3];
    __syncthreads();
    float total = totsh;
    float scale = 1.f / fmaxf(sqrtf(total), 1e-12f);
#pragma unroll
    for (int j = 0; j < 4; ++j) {
        int c = tid + j * 128;
        g_nodes[b][k][c] = t4[j] * scale;
    }
    if (tid == 0) g_row[b][k] = total * scale * scale;
}

// ================= phase 4: global l2norm + output =================
__global__ void phase4_kernel(float* __restrict__ outflat) {
    const int b = blockIdx.x;      // 16
    const int tid = threadIdx.x;   // 256
    __shared__ float red[64];
    __shared__ float gsh;
    if (tid < 64) red[tid] = g_row[b][tid];
    __syncthreads();
    if (tid == 0) {
        float s = 0.f;
#pragma unroll
        for (int i = 0; i < 64; ++i) s += red[i];
        gsh = 1.f / fmaxf(sqrtf(s), 1e-12f);
    }
    __syncthreads();
    float g = gsh;
    const float* np = &g_nodes[b][0][0];
    float* op = outflat + (size_t)b * Kq * Cq;
    for (int i = tid; i < Kq * Cq; i += 256) op[i] = np[i] * g;
}

// ================= launch =================
extern "C" void kernel_launch(void* const* d_in, const int* in_sizes, int n_in,
                              void* d_out, int out_size) {
    const float* x      = (const float*)d_in[0];
    const float* anchor = (const float*)d_in[1];
    const float* sraw   = (const float*)d_in[2];
    float* outf = (float*)d_out;

    const int FLAT = Bq * Cq * Kq;      // 524288
    const int SA   = Bq * Kq * Nq;      // 4194304

    float* sa_dev = nullptr;
    cudaGetSymbolAddress((void**)&sa_dev, g_sa);
    float* nodes_dev = nullptr;
    cudaGetSymbolAddress((void**)&nodes_dev, g_nodes);

    float* sa_ptr;
    float* flat_ptr;
    if (out_size == FLAT) {
        flat_ptr = outf;
        sa_ptr = sa_dev;
    } else if (out_size == SA) {
        sa_ptr = outf;
        flat_ptr = nodes_dev;
    } else {
        flat_ptr = outf;
        sa_ptr = outf + FLAT;
    }

    static bool attr_done = false;
    if (!attr_done) {
        cudaFuncSetAttribute(phase1_kernel,
                             cudaFuncAttributeMaxDynamicSharedMemorySize, P1_SMEM);
        cudaFuncSetAttribute(phase2_kernel,
                             cudaFuncAttributeMaxDynamicSharedMemorySize, P2_SMEM);
        attr_done = true;
    }

    prep_kernel<<<Kq, 256>>>(anchor, sraw);
    phase1_kernel<<<dim3(Nq / 256, Bq), 256, P1_SMEM>>>(x, sa_ptr);
    phase2_kernel<<<dim3(Cq / 256, Bq, 8), 256, P2_SMEM>>>(x);
    phase3_kernel<<<Bq * Kq, 128>>>(anchor);
    phase4_kernel<<<Bq, 256>>>(flat_ptr);
}

// round 14
// speedup vs baseline: 1.1261x; 1.0026x over previous
#include <cuda_runtime.h>
#include <cstdint>

#define Bq 16
#define Cq 512
#define Nq 4096
#define Kq 64

// ================= scratch (static device allocations only) =================
__device__ uint4 gW16[32][512];            // per-16c-chunk fp16 W images (8KB each)
__device__ float gInvS[Kq][Cq];
__device__ float gCst[Kq];
__device__ float g_sa[(size_t)Bq*Kq*Nq];
__device__ uint2 g_sa16b[(size_t)Bq*Kq*256*4]; // hi-only fp16 sa image (8.4MB)
__device__ float g_wsp[Bq][16][Kq];            // per-(b,ntile) wsum partials
__device__ float g_wx8[8][Bq][Kq][Cq];
__device__ float g_row[Bq][Kq];
__device__ float g_nodes[Bq][Kq][Cq];

#define SA_SCALE   2048.0f
#define SA_INV     4.8828125e-4f   // 2^-11

// ================= helpers =================
__device__ __forceinline__ unsigned pk2h(float lo, float hi) {
    unsigned d;
    asm("cvt.rn.f16x2.f32 %0, %1, %2;" : "=r"(d) : "f"(hi), "f"(lo));
    return d;
}
__device__ __forceinline__ float2 unpk2h(unsigned u) {
    float lo, hi;
    asm("{.reg .f16 a,b; mov.b32 {a,b}, %2; cvt.f32.f16 %0, a; cvt.f32.f16 %1, b;}"
        : "=f"(lo), "=f"(hi) : "r"(u));
    return make_float2(lo, hi);
}
// split pair (v0=even slot, v1=odd slot) into fp16x2 hi and lo regs
__device__ __forceinline__ void splitpair(float v0, float v1, unsigned& h, unsigned& l) {
    h = pk2h(v0, v1);
    float2 f = unpk2h(h);
    l = pk2h(v0 - f.x, v1 - f.y);
}
__device__ __forceinline__ void mmaH(float* d, const unsigned* a, const unsigned* b) {
    asm volatile(
        "mma.sync.aligned.m16n8k16.row.col.f32.f16.f16.f32 "
        "{%0,%1,%2,%3}, {%4,%5,%6,%7}, {%8,%9}, {%0,%1,%2,%3};"
        : "+f"(d[0]), "+f"(d[1]), "+f"(d[2]), "+f"(d[3])
        : "r"(a[0]), "r"(a[1]), "r"(a[2]), "r"(a[3]), "r"(b[0]), "r"(b[1]));
}
__device__ __forceinline__ uint32_t smem_u32(const void* p) {
    uint32_t a;
    asm("{ .reg .u64 t; cvta.to.shared.u64 t, %1; cvt.u32.u64 %0, t; }" : "=r"(a) : "l"(p));
    return a;
}
#define CP16(dst, src) asm volatile("cp.async.cg.shared.global [%0], [%1], 16;" :: "r"(dst), "l"(src))
#define CPCOMMIT()     asm volatile("cp.async.commit_group;" ::: "memory")
#define CPWAIT2()      asm volatile("cp.async.wait_group 2;" ::: "memory")
#define CPWAIT1()      asm volatile("cp.async.wait_group 1;" ::: "memory")
#define CPWAIT0()      asm volatile("cp.async.wait_group 0;" ::: "memory")

// ===== phase1: 4 bufs of { A raw x [16c][260f pitch], B fp16 image 8KB } =====
#define P1_BUF   24832u
#define P1_BOFF  16640u
#define P1_SMEM  99328
// ===== phase2: 4 bufs of { A raw x [256c][16n] swizzled 16KB, B hi sa16 2KB } =====
#define P2_BUF   18432u
#define P2_BOFF  16384u
#define P2_SMEM  73728

// ================= prep: sigma, fp16 W images, const =================
__global__ void prep_kernel(const float* __restrict__ anchor,
                            const float* __restrict__ sraw) {
    const int k = blockIdx.x;       // 64
    const int tid = threadIdx.x;    // 256
    float part = 0.f;
#pragma unroll
    for (int jj = 0; jj < 2; ++jj) {
        int c = tid + jj * 256;
        float sr = sraw[k * Cq + c];
        float sg = 1.f / (1.f + __expf(-sr));
        float a  = anchor[k * Cq + c];
        float i2 = 1.f / (sg * sg);
        float w2 = -2.f * a * i2;
        gInvS[k][c] = 1.f / sg;
        part += a * a * i2;
        int ch = c >> 4, cl = c & 15;
        int j = k >> 3, gg = k & 7;
        int q = (cl >> 1) & 3, reg = cl >> 3, half = cl & 1;
        float vals[2] = { i2, w2 };   // step0 = x^2 weight, step1 = x weight
#pragma unroll
        for (int s = 0; s < 2; ++s) {
            unsigned hp, lp;
            splitpair(vals[s], 0.f, hp, lp);
            unsigned short* base =
                (unsigned short*)&gW16[ch][(((s * 8 + j) * 8 + gg) * 4 + q)];
            base[reg * 2 + half]     = (unsigned short)(hp & 0xFFFFu);
            base[4 + reg * 2 + half] = (unsigned short)(lp & 0xFFFFu);
        }
    }
#pragma unroll
    for (int off = 16; off; off >>= 1) part += __shfl_xor_sync(0xffffffffu, part, off);
    __shared__ float red[8];
    if ((tid & 31) == 0) red[tid >> 5] = part;
    __syncthreads();
    if (tid == 0) {
        float s = 0.f;
#pragma unroll
        for (int i = 0; i < 8; ++i) s += red[i];
        gCst[k] = s;
    }
}

// ================= phase 1: distance GEMM (3xFP16 mma) + softmax
//                   + fused sa16/wsum emission. 4-stage cp.async pipeline. =====
__global__ __launch_bounds__(256, 2)
void phase1_kernel(const float* __restrict__ x, float* __restrict__ sa) {
    extern __shared__ char smem[];
    __shared__ float cst[64];
    const uint32_t sb = smem_u32(smem);
    const int tid = threadIdx.x;
    const int w = tid >> 5, lane = tid & 31;
    const int g = lane >> 2, q = lane & 3;
    const int n0w = w << 5;
    const int b  = blockIdx.y;
    const int ntile = blockIdx.x;
    const int n0 = ntile << 8;
    const float* xb = x + (size_t)b * Cq * Nq + n0;
    if (tid < 64) cst[tid] = gCst[tid];

    float acc[2][8][4];
#pragma unroll
    for (int i = 0; i < 2; ++i)
#pragma unroll
        for (int j = 0; j < 8; ++j)
#pragma unroll
            for (int e = 0; e < 4; ++e) acc[i][j][e] = 0.f;

    auto fill = [&](int ch) {
        const uint32_t base = sb + (uint32_t)(ch & 3) * P1_BUF;
        const float* xc = xb + (size_t)(ch << 4) * Nq;
#pragma unroll
        for (int it = 0; it < 4; ++it) {
            int u = tid + (it << 8);
            int row = u >> 6, seg = u & 63;
            CP16(base + (uint32_t)row * 1040u + (uint32_t)(seg << 4),
                 xc + (size_t)row * Nq + (seg << 2));
        }
#pragma unroll
        for (int it = 0; it < 2; ++it) {
            int u = tid + (it << 8);
            CP16(base + P1_BOFF + (uint32_t)(u << 4), &gW16[ch][u]);
        }
        CPCOMMIT();
    };

    auto gemm = [&](int buf) {
        const float* fA = (const float*)(smem + (uint32_t)buf * P1_BUF);
        const uint4* fB = (const uint4*)(smem + (uint32_t)buf * P1_BUF + P1_BOFF);
        float xv[2][8];
#pragma unroll
        for (int i = 0; i < 2; ++i) {
            const float* pa = fA + n0w + (i << 4) + g;
            xv[i][0] = pa[(2 * q) * 260];         xv[i][1] = pa[(2 * q + 1) * 260];
            xv[i][2] = pa[(2 * q + 8) * 260];     xv[i][3] = pa[(2 * q + 9) * 260];
            xv[i][4] = pa[(2 * q) * 260 + 8];     xv[i][5] = pa[(2 * q + 1) * 260 + 8];
            xv[i][6] = pa[(2 * q + 8) * 260 + 8]; xv[i][7] = pa[(2 * q + 9) * 260 + 8];
        }
#pragma unroll
        for (int s = 0; s < 2; ++s) {
            unsigned aH[2][4], aL[2][4];
#pragma unroll
            for (int i = 0; i < 2; ++i) {
                float e0, e1, e2, e3, e4, e5, e6, e7;
                if (s == 0) {
                    e0 = xv[i][0] * xv[i][0]; e1 = xv[i][1] * xv[i][1];
                    e2 = xv[i][2] * xv[i][2]; e3 = xv[i][3] * xv[i][3];
                    e4 = xv[i][4] * xv[i][4]; e5 = xv[i][5] * xv[i][5];
                    e6 = xv[i][6] * xv[i][6]; e7 = xv[i][7] * xv[i][7];
                } else {
                    e0 = xv[i][0]; e1 = xv[i][1]; e2 = xv[i][2]; e3 = xv[i][3];
                    e4 = xv[i][4]; e5 = xv[i][5]; e6 = xv[i][6]; e7 = xv[i][7];
                }
                splitpair(e0, e1, aH[i][0], aL[i][0]);
                splitpair(e4, e5, aH[i][1], aL[i][1]);
                splitpair(e2, e3, aH[i][2], aL[i][2]);
                splitpair(e6, e7, aH[i][3], aL[i][3]);
            }
#pragma unroll
            for (int jb = 0; jb < 2; ++jb) {
                uint4 w4[4];
#pragma unroll
                for (int jj = 0; jj < 4; ++jj)
                    w4[jj] = fB[(((s * 8 + (jb << 2) + jj) * 8 + g) << 2) + q];
#pragma unroll
                for (int jj = 0; jj < 4; ++jj) {
                    unsigned bh[2] = { w4[jj].x, w4[jj].y };
                    mmaH(acc[0][(jb << 2) + jj], aH[0], bh);
                    mmaH(acc[1][(jb << 2) + jj], aH[1], bh);
                }
#pragma unroll
                for (int jj = 0; jj < 4; ++jj) {
                    unsigned bl[2] = { w4[jj].z, w4[jj].w };
                    mmaH(acc[0][(jb << 2) + jj], aH[0], bl);
                    mmaH(acc[1][(jb << 2) + jj], aH[1], bl);
                }
#pragma unroll
                for (int jj = 0; jj < 4; ++jj) {
                    unsigned bh[2] = { w4[jj].x, w4[jj].y };
                    mmaH(acc[0][(jb << 2) + jj], aL[0], bh);
                    mmaH(acc[1][(jb << 2) + jj], aL[1], bh);
                }
            }
        }
    };

    fill(0); fill(1); fill(2);
    for (int ch = 0; ch < 32; ++ch) {
        if (ch + 2 < 32) { CPWAIT2(); } else if (ch + 1 < 32) { CPWAIT1(); } else { CPWAIT0(); }
        __syncthreads();
        if (ch + 3 < 32) fill(ch + 3);
        gemm(ch & 3);
    }
    CPWAIT0();
    __syncthreads();

    // stage d2 in smem (overlays buffers)
    float* d2 = (float*)smem;
#pragma unroll
    for (int i = 0; i < 2; ++i) {
        int r0 = n0w + (i << 4) + g;
#pragma unroll
        for (int j = 0; j < 8; ++j) {
            int kc = (j << 3) + (q << 1);
            *(float2*)&d2[r0 * 66 + kc]       = make_float2(acc[i][j][0], acc[i][j][1]);
            *(float2*)&d2[(r0 + 8) * 66 + kc] = make_float2(acc[i][j][2], acc[i][j][3]);
        }
    }
    __syncthreads();

    // softmax: one thread per n (p values kept in e[])
    float e[64];
    {
#pragma unroll
        for (int k = 0; k < 64; ++k) e[k] = d2[tid * 66 + k] + cst[k];
        float mn = e[0];
#pragma unroll
        for (int k = 1; k < 64; ++k) mn = fminf(mn, e[k]);
        float s = 0.f;
#pragma unroll
        for (int k = 0; k < 64; ++k) {
            float t = __expf(-0.5f * (e[k] - mn));
            e[k] = t;
            s += t;
        }
        float r = 1.f / s;
#pragma unroll
        for (int k = 0; k < 64; ++k) e[k] *= r;
    }
    __syncthreads();   // all d2 reads done before overwrite

    // transpose p into [k][256] (pitch 264), write sa fp32
    float* psh = (float*)smem;
#pragma unroll
    for (int k = 0; k < 64; ++k) psh[k * 264 + tid] = e[k];
    {
        float* sp = sa + (size_t)b * Kq * Nq + n0 + tid;
#pragma unroll
        for (int k = 0; k < 64; ++k) sp[(size_t)k * Nq] = e[k];
    }
    __syncthreads();

    // build hi-only fp16 sa image + wsum partials. unit u = (k, ch16)
    float* wssh = (float*)(smem + 67584);
#pragma unroll
    for (int it = 0; it < 4; ++it) {
        int u = tid + (it << 8);
        int k = u >> 4, ch = u & 15;
        const float* src = psh + k * 264 + (ch << 4);
        float4 v0 = *(const float4*)(src);
        float4 v1 = *(const float4*)(src + 4);
        float4 v2 = *(const float4*)(src + 8);
        float4 v3 = *(const float4*)(src + 12);
        uint4 oA, oB;
        oA.x = pk2h(v0.x * SA_SCALE, v0.y * SA_SCALE);
        oA.y = pk2h(v2.x * SA_SCALE, v2.y * SA_SCALE);
        oA.z = pk2h(v0.z * SA_SCALE, v0.w * SA_SCALE);
        oA.w = pk2h(v2.z * SA_SCALE, v2.w * SA_SCALE);
        oB.x = pk2h(v1.x * SA_SCALE, v1.y * SA_SCALE);
        oB.y = pk2h(v3.x * SA_SCALE, v3.y * SA_SCALE);
        oB.z = pk2h(v1.z * SA_SCALE, v1.w * SA_SCALE);
        oB.w = pk2h(v3.z * SA_SCALE, v3.w * SA_SCALE);
        size_t dstbase = ((size_t)((b * 64 + k) * 256 + (ntile << 4) + ch)) << 2;
        *(uint4*)&g_sa16b[dstbase]     = oA;   // qq 0,1
        *(uint4*)&g_sa16b[dstbase + 2] = oB;   // qq 2,3
        float sA = ((v0.x + v0.y) + (v0.z + v0.w)) + ((v1.x + v1.y) + (v1.z + v1.w));
        float sB = ((v2.x + v2.y) + (v2.z + v2.w)) + ((v3.x + v3.y) + (v3.z + v3.w));
        wssh[u] = sA + sB;
    }
    __syncthreads();
    if (tid < 64) {
        float s = 0.f;
#pragma unroll
        for (int c = 0; c < 16; ++c) s += wssh[tid * 16 + c];
        g_wsp[b][ntile][tid] = s;
    }
}

// ================= phase 2: wx[c,k] = sum_n x[c,n]*sa16[k,n]  (2-pass fp16)
//                   4-stage cp.async pipeline. =================
__global__ __launch_bounds__(256, 2)
void phase2_kernel(const float* __restrict__ x) {
    extern __shared__ char smem[];
    const uint32_t sb = smem_u32(smem);
    const int tid = threadIdx.x;
    const int w = tid >> 5, lane = tid & 31;
    const int g = lane >> 2, q = lane & 3;
    const int c0w = w << 5;
    const int c0 = (int)blockIdx.x << 8;
    const int b  = blockIdx.y;
    const int seg = blockIdx.z;
    const int n0 = seg << 9;
    const float* xb = x + ((size_t)b * Cq + c0) * Nq + n0;

    float acc[2][8][4];
#pragma unroll
    for (int i = 0; i < 2; ++i)
#pragma unroll
        for (int j = 0; j < 8; ++j)
#pragma unroll
            for (int e = 0; e < 4; ++e) acc[i][j][e] = 0.f;

    auto fill = [&](int ch) {
        const uint32_t base = sb + (uint32_t)(ch & 3) * P2_BUF;
        const int nn = ch << 4;
        // A: 256 rows(c) x 16n, 64B rows with 16B-seg XOR swizzle
#pragma unroll
        for (int it = 0; it < 4; ++it) {
            int u = tid + (it << 8);
            int row = u >> 2, sg2 = u & 3;
            CP16(base + (uint32_t)(row << 6) + (uint32_t)((sg2 ^ ((row >> 1) & 3)) << 4),
                 xb + (size_t)row * Nq + nn + (sg2 << 2));
        }
        // B: hi-only sa16, 128 x 16B
        if (tid < 128) {
            int node = tid >> 1, qq2 = tid & 1;
            CP16(base + P2_BOFF + (uint32_t)(tid << 4),
                 &g_sa16b[(((size_t)((b * 64 + node) * 256 + (seg << 5) + ch)) << 2) + (qq2 << 1)]);
        }
        CPCOMMIT();
    };

    auto gemm = [&](int buf) {
        const float* fA = (const float*)(smem + (uint32_t)buf * P2_BUF);
        const uint2* fB = (const uint2*)(smem + (uint32_t)buf * P2_BUF + P2_BOFF);
        unsigned aH[2][4], aL[2][4];
#pragma unroll
        for (int i = 0; i < 2; ++i) {
            int r0 = c0w + (i << 4) + g;
            int r1 = r0 + 8;
            int k0 = ((r0 >> 1) & 3) << 2;
            int k1 = ((r1 >> 1) & 3) << 2;
            float2 p00 = *(const float2*)(fA + (r0 << 4) + ((2 * q) ^ k0));
            float2 p01 = *(const float2*)(fA + (r0 << 4) + ((2 * q + 8) ^ k0));
            float2 p10 = *(const float2*)(fA + (r1 << 4) + ((2 * q) ^ k1));
            float2 p11 = *(const float2*)(fA + (r1 << 4) + ((2 * q + 8) ^ k1));
            splitpair(p00.x, p00.y, aH[i][0], aL[i][0]);
            splitpair(p10.x, p10.y, aH[i][1], aL[i][1]);
            splitpair(p01.x, p01.y, aH[i][2], aL[i][2]);
            splitpair(p11.x, p11.y, aH[i][3], aL[i][3]);
        }
#pragma unroll
        for (int jb = 0; jb < 2; ++jb) {
            uint2 w2[4];
#pragma unroll
            for (int jj = 0; jj < 4; ++jj)
                w2[jj] = fB[(((((jb << 2) + jj) << 3) + g) << 2) + q];
#pragma unroll
            for (int jj = 0; jj < 4; ++jj) {
                unsigned bh[2] = { w2[jj].x, w2[jj].y };
                mmaH(acc[0][(jb << 2) + jj], aH[0], bh);
                mmaH(acc[1][(jb << 2) + jj], aH[1], bh);
            }
#pragma unroll
            for (int jj = 0; jj < 4; ++jj) {
                unsigned bh[2] = { w2[jj].x, w2[jj].y };
                mmaH(acc[0][(jb << 2) + jj], aL[0], bh);
                mmaH(acc[1][(jb << 2) + jj], aL[1], bh);
            }
        }
    };

    fill(0); fill(1); fill(2);
    for (int ch = 0; ch < 32; ++ch) {
        if (ch + 2 < 32) { CPWAIT2(); } else if (ch + 1 < 32) { CPWAIT1(); } else { CPWAIT0(); }
        __syncthreads();
        if (ch + 3 < 32) fill(ch + 3);
        gemm(ch & 3);
    }

    // epilogue: unscale by 2^-11, scatter D[c,k] partials
    float* basep = &g_wx8[seg][b][0][0];
#pragma unroll
    for (int j = 0; j < 8; ++j) {
        int kc = (j << 3) + (q << 1);
#pragma unroll
        for (int i = 0; i < 2; ++i) {
            int cc = c0 + c0w + (i << 4) + g;
            basep[(size_t)kc * Cq + cc]           = acc[i][j][0] * SA_INV;
            basep[(size_t)(kc + 1) * Cq + cc]     = acc[i][j][1] * SA_INV;
            basep[(size_t)kc * Cq + cc + 8]       = acc[i][j][2] * SA_INV;
            basep[(size_t)(kc + 1) * Cq + cc + 8] = acc[i][j][3] * SA_INV;
        }
    }
}

// ================= phase 3: nodes + per-row l2norm =================
__global__ void phase3_kernel(const float* __restrict__ anchor) {
    const int bk = blockIdx.x;     // 1024
    const int b = bk >> 6, k = bk & 63;
    const int tid = threadIdx.x;   // 128
    float wsv = 0.f;
#pragma unroll
    for (int t = 0; t < 16; ++t) wsv += g_wsp[b][t][k];
    const float invw = 1.f / (wsv + 1e-9f);
    float t4[4];
    float ssq = 0.f;
#pragma unroll
    for (int j = 0; j < 4; ++j) {
        int c = tid + j * 128;
        float wx = 0.f;
#pragma unroll
        for (int s = 0; s < 8; ++s) wx += g_wx8[s][b][k][c];
        float nd = (wx - wsv * anchor[k * Cq + c]) * gInvS[k][c] * invw;
        t4[j] = nd;
        ssq += nd * nd;
    }
#pragma unroll
    for (int off = 16; off; off >>= 1) ssq += __shfl_xor_sync(0xffffffffu, ssq, off);
    __shared__ float red[4];
    __shared__ float totsh;
    if ((tid & 31) == 0) red[tid >> 5] = ssq;
    __syncthreads();
    if (tid == 0) totsh = red[0] + red[1] + red[2] + red[3];
    __syncthreads();
    float total = totsh;
    float scale = 1.f / fmaxf(sqrtf(total), 1e-12f);
#pragma unroll
    for (int j = 0; j < 4; ++j) {
        int c = tid + j * 128;
        g_nodes[b][k][c] = t4[j] * scale;
    }
    if (tid == 0) g_row[b][k] = total * scale * scale;
}

// ================= phase 4: global l2norm + output =================
__global__ void phase4_kernel(float* __restrict__ outflat) {
    const int b = blockIdx.x;      // 16
    const int tid = threadIdx.x;   // 256
    __shared__ float red[64];
    __shared__ float gsh;
    if (tid < 64) red[tid] = g_row[b][tid];
    __syncthreads();
    if (tid == 0) {
        float s = 0.f;
#pragma unroll
        for (int i = 0; i < 64; ++i) s += red[i];
        gsh = 1.f / fmaxf(sqrtf(s), 1e-12f);
    }
    __syncthreads();
    float g = gsh;
    const float* np = &g_nodes[b][0][0];
    float* op = outflat + (size_t)b * Kq * Cq;
    for (int i = tid; i < Kq * Cq; i += 256) op[i] = np[i] * g;
}

// ================= launch =================
extern "C" void kernel_launch(void* const* d_in, const int* in_sizes, int n_in,
                              void* d_out, int out_size) {
    const float* x      = (const float*)d_in[0];
    const float* anchor = (const float*)d_in[1];
    const float* sraw   = (const float*)d_in[2];
    float* outf = (float*)d_out;

    const int FLAT = Bq * Cq * Kq;      // 524288
    const int SA   = Bq * Kq * Nq;      // 4194304

    float* sa_dev = nullptr;
    cudaGetSymbolAddress((void**)&sa_dev, g_sa);
    float* nodes_dev = nullptr;
    cudaGetSymbolAddress((void**)&nodes_dev, g_nodes);

    float* sa_ptr;
    float* flat_ptr;
    if (out_size == FLAT) {
        flat_ptr = outf;
        sa_ptr = sa_dev;
    } else if (out_size == SA) {
        sa_ptr = outf;
        flat_ptr = nodes_dev;
    } else {
        flat_ptr = outf;
        sa_ptr = outf + FLAT;
    }

    static bool attr_done = false;
    if (!attr_done) {
        cudaFuncSetAttribute(phase1_kernel,
                             cudaFuncAttributeMaxDynamicSharedMemorySize, P1_SMEM);
        cudaFuncSetAttribute(phase2_kernel,
                             cudaFuncAttributeMaxDynamicSharedMemorySize, P2_SMEM);
        attr_done = true;
    }

    prep_kernel<<<Kq, 256>>>(anchor, sraw);
    phase1_kernel<<<dim3(Nq / 256, Bq), 256, P1_SMEM>>>(x, sa_ptr);
    phase2_kernel<<<dim3(Cq / 256, Bq, 8), 256, P2_SMEM>>>(x);
    phase3_kernel<<<Bq * Kq, 128>>>(anchor);
    phase4_kernel<<<Bq, 256>>>(flat_ptr);
}

// round 15
// speedup vs baseline: 1.1410x; 1.0132x over previous
#include <cuda_runtime.h>
#include <cstdint>

#define Bq 16
#define Cq 512
#define Nq 4096
#define Kq 64

// ================= scratch (static device allocations only) =================
__device__ uint4 gW16[32][512];            // per-16c-chunk fp16 W images (8KB each)
__device__ float gInvS[Kq][Cq];
__device__ float gCst[Kq];
__device__ float g_sa[(size_t)Bq*Kq*Nq];
__device__ uint2 g_sa16b[(size_t)Bq*Kq*256*4]; // hi-only fp16 sa image (8.4MB)
__device__ float g_wsp[Bq][16][Kq];            // per-(b,ntile) wsum partials
__device__ float g_wx8[8][Bq][Kq][Cq];
__device__ float g_row[Bq][Kq];
__device__ float g_nodes[Bq][Kq][Cq];

#define SA_SCALE   2048.0f
#define SA_INV     4.8828125e-4f   // 2^-11

// ================= helpers =================
__device__ __forceinline__ unsigned pk2h(float lo, float hi) {
    unsigned d;
    asm("cvt.rn.f16x2.f32 %0, %1, %2;" : "=r"(d) : "f"(hi), "f"(lo));
    return d;
}
__device__ __forceinline__ float2 unpk2h(unsigned u) {
    float lo, hi;
    asm("{.reg .f16 a,b; mov.b32 {a,b}, %2; cvt.f32.f16 %0, a; cvt.f32.f16 %1, b;}"
        : "=f"(lo), "=f"(hi) : "r"(u));
    return make_float2(lo, hi);
}
// split pair (v0=even slot, v1=odd slot) into fp16x2 hi and lo regs
__device__ __forceinline__ void splitpair(float v0, float v1, unsigned& h, unsigned& l) {
    h = pk2h(v0, v1);
    float2 f = unpk2h(h);
    l = pk2h(v0 - f.x, v1 - f.y);
}
__device__ __forceinline__ void mmaH(float* d, const unsigned* a, const unsigned* b) {
    asm volatile(
        "mma.sync.aligned.m16n8k16.row.col.f32.f16.f16.f32 "
        "{%0,%1,%2,%3}, {%4,%5,%6,%7}, {%8,%9}, {%0,%1,%2,%3};"
        : "+f"(d[0]), "+f"(d[1]), "+f"(d[2]), "+f"(d[3])
        : "r"(a[0]), "r"(a[1]), "r"(a[2]), "r"(a[3]), "r"(b[0]), "r"(b[1]));
}
__device__ __forceinline__ uint32_t smem_u32(const void* p) {
    uint32_t a;
    asm("{ .reg .u64 t; cvta.to.shared.u64 t, %1; cvt.u32.u64 %0, t; }" : "=r"(a) : "l"(p));
    return a;
}
#define CP16(dst, src) asm volatile("cp.async.cg.shared.global [%0], [%1], 16;" :: "r"(dst), "l"(src))
#define CPCOMMIT()     asm volatile("cp.async.commit_group;" ::: "memory")
#define CPWAIT2()      asm volatile("cp.async.wait_group 2;" ::: "memory")
#define CPWAIT1()      asm volatile("cp.async.wait_group 1;" ::: "memory")
#define CPWAIT0()      asm volatile("cp.async.wait_group 0;" ::: "memory")

// ===== phase1: 4 bufs of { A raw x [16c][260f pitch], B fp16 image 8KB } =====
#define P1_BUF   24832u
#define P1_BOFF  16640u
#define P1_SMEM  99328
// ===== phase2: 4 bufs of { A raw x [256c][16n] swizzled 16KB, B hi sa16 2KB } =====
#define P2_BUF   18432u
#define P2_BOFF  16384u
#define P2_SMEM  73728

// ================= prep: sigma, fp16 W images, const =================
__global__ void prep_kernel(const float* __restrict__ anchor,
                            const float* __restrict__ sraw) {
    const int k = blockIdx.x;       // 64
    const int tid = threadIdx.x;    // 256
    float part = 0.f;
#pragma unroll
    for (int jj = 0; jj < 2; ++jj) {
        int c = tid + jj * 256;
        float sr = sraw[k * Cq + c];
        float sg = 1.f / (1.f + __expf(-sr));
        float a  = anchor[k * Cq + c];
        float i2 = 1.f / (sg * sg);
        float w2 = -2.f * a * i2;
        gInvS[k][c] = 1.f / sg;
        part += a * a * i2;
        int ch = c >> 4, cl = c & 15;
        int j = k >> 3, gg = k & 7;
        int q = (cl >> 1) & 3, reg = cl >> 3, half = cl & 1;
        float vals[2] = { i2, w2 };   // step0 = x^2 weight, step1 = x weight
#pragma unroll
        for (int s = 0; s < 2; ++s) {
            unsigned hp, lp;
            splitpair(vals[s], 0.f, hp, lp);
            unsigned short* base =
                (unsigned short*)&gW16[ch][(((s * 8 + j) * 8 + gg) * 4 + q)];
            base[reg * 2 + half]     = (unsigned short)(hp & 0xFFFFu);
            base[4 + reg * 2 + half] = (unsigned short)(lp & 0xFFFFu);
        }
    }
#pragma unroll
    for (int off = 16; off; off >>= 1) part += __shfl_xor_sync(0xffffffffu, part, off);
    __shared__ float red[8];
    if ((tid & 31) == 0) red[tid >> 5] = part;
    __syncthreads();
    if (tid == 0) {
        float s = 0.f;
#pragma unroll
        for (int i = 0; i < 8; ++i) s += red[i];
        gCst[k] = s;
    }
}

// ================= phase 1: distance GEMM (3xFP16 mma) + softmax
//                   + fused sa16/wsum emission. 4-stage cp.async pipeline. =====
__global__ __launch_bounds__(256, 2)
void phase1_kernel(const float* __restrict__ x, float* __restrict__ sa) {
    extern __shared__ char smem[];
    __shared__ float cst[64];
    const uint32_t sb = smem_u32(smem);
    const int tid = threadIdx.x;
    const int w = tid >> 5, lane = tid & 31;
    const int g = lane >> 2, q = lane & 3;
    const int n0w = w << 5;
    const int b  = blockIdx.y;
    const int ntile = blockIdx.x;
    const int n0 = ntile << 8;
    const float* xb = x + (size_t)b * Cq * Nq + n0;
    if (tid < 64) cst[tid] = gCst[tid];

    float acc[2][8][4];
#pragma unroll
    for (int i = 0; i < 2; ++i)
#pragma unroll
        for (int j = 0; j < 8; ++j)
#pragma unroll
            for (int e = 0; e < 4; ++e) acc[i][j][e] = 0.f;

    auto fill = [&](int ch) {
        const uint32_t base = sb + (uint32_t)(ch & 3) * P1_BUF;
        const float* xc = xb + (size_t)(ch << 4) * Nq;
#pragma unroll
        for (int it = 0; it < 4; ++it) {
            int u = tid + (it << 8);
            int row = u >> 6, seg = u & 63;
            CP16(base + (uint32_t)row * 1040u + (uint32_t)(seg << 4),
                 xc + (size_t)row * Nq + (seg << 2));
        }
#pragma unroll
        for (int it = 0; it < 2; ++it) {
            int u = tid + (it << 8);
            CP16(base + P1_BOFF + (uint32_t)(u << 4), &gW16[ch][u]);
        }
        CPCOMMIT();
    };

    auto gemm = [&](int buf) {
        const float* fA = (const float*)(smem + (uint32_t)buf * P1_BUF);
        const uint4* fB = (const uint4*)(smem + (uint32_t)buf * P1_BUF + P1_BOFF);
        float xv[2][8];
#pragma unroll
        for (int i = 0; i < 2; ++i) {
            const float* pa = fA + n0w + (i << 4) + g;
            xv[i][0] = pa[(2 * q) * 260];         xv[i][1] = pa[(2 * q + 1) * 260];
            xv[i][2] = pa[(2 * q + 8) * 260];     xv[i][3] = pa[(2 * q + 9) * 260];
            xv[i][4] = pa[(2 * q) * 260 + 8];     xv[i][5] = pa[(2 * q + 1) * 260 + 8];
            xv[i][6] = pa[(2 * q + 8) * 260 + 8]; xv[i][7] = pa[(2 * q + 9) * 260 + 8];
        }
#pragma unroll
        for (int s = 0; s < 2; ++s) {
            unsigned aH[2][4], aL[2][4];
#pragma unroll
            for (int i = 0; i < 2; ++i) {
                float e0, e1, e2, e3, e4, e5, e6, e7;
                if (s == 0) {
                    e0 = xv[i][0] * xv[i][0]; e1 = xv[i][1] * xv[i][1];
                    e2 = xv[i][2] * xv[i][2]; e3 = xv[i][3] * xv[i][3];
                    e4 = xv[i][4] * xv[i][4]; e5 = xv[i][5] * xv[i][5];
                    e6 = xv[i][6] * xv[i][6]; e7 = xv[i][7] * xv[i][7];
                } else {
                    e0 = xv[i][0]; e1 = xv[i][1]; e2 = xv[i][2]; e3 = xv[i][3];
                    e4 = xv[i][4]; e5 = xv[i][5]; e6 = xv[i][6]; e7 = xv[i][7];
                }
                splitpair(e0, e1, aH[i][0], aL[i][0]);
                splitpair(e4, e5, aH[i][1], aL[i][1]);
                splitpair(e2, e3, aH[i][2], aL[i][2]);
                splitpair(e6, e7, aH[i][3], aL[i][3]);
            }
#pragma unroll
            for (int jb = 0; jb < 2; ++jb) {
                uint4 w4[4];
#pragma unroll
                for (int jj = 0; jj < 4; ++jj)
                    w4[jj] = fB[(((s * 8 + (jb << 2) + jj) * 8 + g) << 2) + q];
#pragma unroll
                for (int jj = 0; jj < 4; ++jj) {
                    unsigned bh[2] = { w4[jj].x, w4[jj].y };
                    mmaH(acc[0][(jb << 2) + jj], aH[0], bh);
                    mmaH(acc[1][(jb << 2) + jj], aH[1], bh);
                }
#pragma unroll
                for (int jj = 0; jj < 4; ++jj) {
                    unsigned bl[2] = { w4[jj].z, w4[jj].w };
                    mmaH(acc[0][(jb << 2) + jj], aH[0], bl);
                    mmaH(acc[1][(jb << 2) + jj], aH[1], bl);
                }
#pragma unroll
                for (int jj = 0; jj < 4; ++jj) {
                    unsigned bh[2] = { w4[jj].x, w4[jj].y };
                    mmaH(acc[0][(jb << 2) + jj], aL[0], bh);
                    mmaH(acc[1][(jb << 2) + jj], aL[1], bh);
                }
            }
        }
    };

    fill(0); fill(1); fill(2);
    for (int ch = 0; ch < 32; ++ch) {
        if (ch + 2 < 32) { CPWAIT2(); } else if (ch + 1 < 32) { CPWAIT1(); } else { CPWAIT0(); }
        __syncthreads();
        if (ch + 3 < 32) fill(ch + 3);
        gemm(ch & 3);
    }
    CPWAIT0();
    __syncthreads();

    // stage d2 in smem (overlays buffers)
    float* d2 = (float*)smem;
#pragma unroll
    for (int i = 0; i < 2; ++i) {
        int r0 = n0w + (i << 4) + g;
#pragma unroll
        for (int j = 0; j < 8; ++j) {
            int kc = (j << 3) + (q << 1);
            *(float2*)&d2[r0 * 66 + kc]       = make_float2(acc[i][j][0], acc[i][j][1]);
            *(float2*)&d2[(r0 + 8) * 66 + kc] = make_float2(acc[i][j][2], acc[i][j][3]);
        }
    }
    __syncthreads();

    // softmax: one thread per n (p values kept in e[])
    float e[64];
    {
#pragma unroll
        for (int k = 0; k < 64; ++k) e[k] = d2[tid * 66 + k] + cst[k];
        float mn = e[0];
#pragma unroll
        for (int k = 1; k < 64; ++k) mn = fminf(mn, e[k]);
        float s = 0.f;
#pragma unroll
        for (int k = 0; k < 64; ++k) {
            float t = __expf(-0.5f * (e[k] - mn));
            e[k] = t;
            s += t;
        }
        float r = 1.f / s;
#pragma unroll
        for (int k = 0; k < 64; ++k) e[k] *= r;
    }
    __syncthreads();   // all d2 reads done before overwrite

    // transpose p into [k][256] (pitch 264), write sa fp32
    float* psh = (float*)smem;
#pragma unroll
    for (int k = 0; k < 64; ++k) psh[k * 264 + tid] = e[k];
    {
        float* sp = sa + (size_t)b * Kq * Nq + n0 + tid;
#pragma unroll
        for (int k = 0; k < 64; ++k) sp[(size_t)k * Nq] = e[k];
    }
    __syncthreads();

    // build hi-only fp16 sa image + wsum partials. unit u = (k, ch16)
    float* wssh = (float*)(smem + 67584);
#pragma unroll
    for (int it = 0; it < 4; ++it) {
        int u = tid + (it << 8);
        int k = u >> 4, ch = u & 15;
        const float* src = psh + k * 264 + (ch << 4);
        float4 v0 = *(const float4*)(src);
        float4 v1 = *(const float4*)(src + 4);
        float4 v2 = *(const float4*)(src + 8);
        float4 v3 = *(const float4*)(src + 12);
        uint4 oA, oB;
        oA.x = pk2h(v0.x * SA_SCALE, v0.y * SA_SCALE);
        oA.y = pk2h(v2.x * SA_SCALE, v2.y * SA_SCALE);
        oA.z = pk2h(v0.z * SA_SCALE, v0.w * SA_SCALE);
        oA.w = pk2h(v2.z * SA_SCALE, v2.w * SA_SCALE);
        oB.x = pk2h(v1.x * SA_SCALE, v1.y * SA_SCALE);
        oB.y = pk2h(v3.x * SA_SCALE, v3.y * SA_SCALE);
        oB.z = pk2h(v1.z * SA_SCALE, v1.w * SA_SCALE);
        oB.w = pk2h(v3.z * SA_SCALE, v3.w * SA_SCALE);
        size_t dstbase = ((size_t)((b * 64 + k) * 256 + (ntile << 4) + ch)) << 2;
        *(uint4*)&g_sa16b[dstbase]     = oA;   // qq 0,1
        *(uint4*)&g_sa16b[dstbase + 2] = oB;   // qq 2,3
        float sA = ((v0.x + v0.y) + (v0.z + v0.w)) + ((v1.x + v1.y) + (v1.z + v1.w));
        float sB = ((v2.x + v2.y) + (v2.z + v2.w)) + ((v3.x + v3.y) + (v3.z + v3.w));
        wssh[u] = sA + sB;
    }
    __syncthreads();
    if (tid < 64) {
        float s = 0.f;
#pragma unroll
        for (int c = 0; c < 16; ++c) s += wssh[tid * 16 + c];
        g_wsp[b][ntile][tid] = s;
    }
}

// ================= phase 2: wx[c,k] = sum_n x[c,n]*sa16[k,n]  (1-pass fp16)
//                   x hi-only (quantization averages out over 4096 n). =========
__global__ __launch_bounds__(256, 2)
void phase2_kernel(const float* __restrict__ x) {
    extern __shared__ char smem[];
    const uint32_t sb = smem_u32(smem);
    const int tid = threadIdx.x;
    const int w = tid >> 5, lane = tid & 31;
    const int g = lane >> 2, q = lane & 3;
    const int c0w = w << 5;
    const int c0 = (int)blockIdx.x << 8;
    const int b  = blockIdx.y;
    const int seg = blockIdx.z;
    const int n0 = seg << 9;
    const float* xb = x + ((size_t)b * Cq + c0) * Nq + n0;

    float acc[2][8][4];
#pragma unroll
    for (int i = 0; i < 2; ++i)
#pragma unroll
        for (int j = 0; j < 8; ++j)
#pragma unroll
            for (int e = 0; e < 4; ++e) acc[i][j][e] = 0.f;

    auto fill = [&](int ch) {
        const uint32_t base = sb + (uint32_t)(ch & 3) * P2_BUF;
        const int nn = ch << 4;
        // A: 256 rows(c) x 16n, 64B rows with 16B-seg XOR swizzle
#pragma unroll
        for (int it = 0; it < 4; ++it) {
            int u = tid + (it << 8);
            int row = u >> 2, sg2 = u & 3;
            CP16(base + (uint32_t)(row << 6) + (uint32_t)((sg2 ^ ((row >> 1) & 3)) << 4),
                 xb + (size_t)row * Nq + nn + (sg2 << 2));
        }
        // B: hi-only sa16, 128 x 16B
        if (tid < 128) {
            int node = tid >> 1, qq2 = tid & 1;
            CP16(base + P2_BOFF + (uint32_t)(tid << 4),
                 &g_sa16b[(((size_t)((b * 64 + node) * 256 + (seg << 5) + ch)) << 2) + (qq2 << 1)]);
        }
        CPCOMMIT();
    };

    auto gemm = [&](int buf) {
        const float* fA = (const float*)(smem + (uint32_t)buf * P2_BUF);
        const uint2* fB = (const uint2*)(smem + (uint32_t)buf * P2_BUF + P2_BOFF);
        unsigned aH[2][4];
#pragma unroll
        for (int i = 0; i < 2; ++i) {
            int r0 = c0w + (i << 4) + g;
            int r1 = r0 + 8;
            int k0 = ((r0 >> 1) & 3) << 2;
            int k1 = ((r1 >> 1) & 3) << 2;
            float2 p00 = *(const float2*)(fA + (r0 << 4) + ((2 * q) ^ k0));
            float2 p01 = *(const float2*)(fA + (r0 << 4) + ((2 * q + 8) ^ k0));
            float2 p10 = *(const float2*)(fA + (r1 << 4) + ((2 * q) ^ k1));
            float2 p11 = *(const float2*)(fA + (r1 << 4) + ((2 * q + 8) ^ k1));
            aH[i][0] = pk2h(p00.x, p00.y);
            aH[i][1] = pk2h(p10.x, p10.y);
            aH[i][2] = pk2h(p01.x, p01.y);
            aH[i][3] = pk2h(p11.x, p11.y);
        }
#pragma unroll
        for (int jb = 0; jb < 2; ++jb) {
            uint2 w2[4];
#pragma unroll
            for (int jj = 0; jj < 4; ++jj)
                w2[jj] = fB[(((((jb << 2) + jj) << 3) + g) << 2) + q];
#pragma unroll
            for (int jj = 0; jj < 4; ++jj) {
                unsigned bh[2] = { w2[jj].x, w2[jj].y };
                mmaH(acc[0][(jb << 2) + jj], aH[0], bh);
                mmaH(acc[1][(jb << 2) + jj], aH[1], bh);
            }
        }
    };

    fill(0); fill(1); fill(2);
    for (int ch = 0; ch < 32; ++ch) {
        if (ch + 2 < 32) { CPWAIT2(); } else if (ch + 1 < 32) { CPWAIT1(); } else { CPWAIT0(); }
        __syncthreads();
        if (ch + 3 < 32) fill(ch + 3);
        gemm(ch & 3);
    }

    // epilogue: unscale by 2^-11, scatter D[c,k] partials
    float* basep = &g_wx8[seg][b][0][0];
#pragma unroll
    for (int j = 0; j < 8; ++j) {
        int kc = (j << 3) + (q << 1);
#pragma unroll
        for (int i = 0; i < 2; ++i) {
            int cc = c0 + c0w + (i << 4) + g;
            basep[(size_t)kc * Cq + cc]           = acc[i][j][0] * SA_INV;
            basep[(size_t)(kc + 1) * Cq + cc]     = acc[i][j][1] * SA_INV;
            basep[(size_t)kc * Cq + cc + 8]       = acc[i][j][2] * SA_INV;
            basep[(size_t)(kc + 1) * Cq + cc + 8] = acc[i][j][3] * SA_INV;
        }
    }
}

// ================= phase 3: nodes + per-row l2norm =================
__global__ void phase3_kernel(const float* __restrict__ anchor) {
    const int bk = blockIdx.x;     // 1024
    const int b = bk >> 6, k = bk & 63;
    const int tid = threadIdx.x;   // 128
    float wsv = 0.f;
#pragma unroll
    for (int t = 0; t < 16; ++t) wsv += g_wsp[b][t][k];
    const float invw = 1.f / (wsv + 1e-9f);
    float t4[4];
    float ssq = 0.f;
#pragma unroll
    for (int j = 0; j < 4; ++j) {
        int c = tid + j * 128;
        float wx = 0.f;
#pragma unroll
        for (int s = 0; s < 8; ++s) wx += g_wx8[s][b][k][c];
        float nd = (wx - wsv * anchor[k * Cq + c]) * gInvS[k][c] * invw;
        t4[j] = nd;
        ssq += nd * nd;
    }
#pragma unroll
    for (int off = 16; off; off >>= 1) ssq += __shfl_xor_sync(0xffffffffu, ssq, off);
    __shared__ float red[4];
    __shared__ float totsh;
    if ((tid & 31) == 0) red[tid >> 5] = ssq;
    __syncthreads();
    if (tid == 0) totsh = red[0] + red[1] + red[2] + red[3];
    __syncthreads();
    float total = totsh;
    float scale = 1.f / fmaxf(sqrtf(total), 1e-12f);
#pragma unroll
    for (int j = 0; j < 4; ++j) {
        int c = tid + j * 128;
        g_nodes[b][k][c] = t4[j] * scale;
    }
    if (tid == 0) g_row[b][k] = total * scale * scale;
}

// ================= phase 4: global l2norm + output =================
__global__ void phase4_kernel(float* __restrict__ outflat) {
    const int b = blockIdx.x;      // 16
    const int tid = threadIdx.x;   // 256
    __shared__ float red[64];
    __shared__ float gsh;
    if (tid < 64) red[tid] = g_row[b][tid];
    __syncthreads();
    if (tid == 0) {
        float s = 0.f;
#pragma unroll
        for (int i = 0; i < 64; ++i) s += red[i];
        gsh = 1.f / fmaxf(sqrtf(s), 1e-12f);
    }
    __syncthreads();
    float g = gsh;
    const float* np = &g_nodes[b][0][0];
    float* op = outflat + (size_t)b * Kq * Cq;
    for (int i = tid; i < Kq * Cq; i += 256) op[i] = np[i] * g;
}

// ================= launch =================
extern "C" void kernel_launch(void* const* d_in, const int* in_sizes, int n_in,
                              void* d_out, int out_size) {
    const float* x      = (const float*)d_in[0];
    const float* anchor = (const float*)d_in[1];
    const float* sraw   = (const float*)d_in[2];
    float* outf = (float*)d_out;

    const int FLAT = Bq * Cq * Kq;      // 524288
    const int SA   = Bq * Kq * Nq;      // 4194304

    float* sa_dev = nullptr;
    cudaGetSymbolAddress((void**)&sa_dev, g_sa);
    float* nodes_dev = nullptr;
    cudaGetSymbolAddress((void**)&nodes_dev, g_nodes);

    float* sa_ptr;
    float* flat_ptr;
    if (out_size == FLAT) {
        flat_ptr = outf;
        sa_ptr = sa_dev;
    } else if (out_size == SA) {
        sa_ptr = outf;
        flat_ptr = nodes_dev;
    } else {
        flat_ptr = outf;
        sa_ptr = outf + FLAT;
    }

    static bool attr_done = false;
    if (!attr_done) {
        cudaFuncSetAttribute(phase1_kernel,
                             cudaFuncAttributeMaxDynamicSharedMemorySize, P1_SMEM);
        cudaFuncSetAttribute(phase2_kernel,
                             cudaFuncAttributeMaxDynamicSharedMemorySize, P2_SMEM);
        attr_done = true;
    }

    prep_kernel<<<Kq, 256>>>(anchor, sraw);
    phase1_kernel<<<dim3(Nq / 256, Bq), 256, P1_SMEM>>>(x, sa_ptr);
    phase2_kernel<<<dim3(Cq / 256, Bq, 8), 256, P2_SMEM>>>(x);
    phase3_kernel<<<Bq * Kq, 128>>>(anchor);
    phase4_kernel<<<Bq, 256>>>(flat_ptr);
}

// round 16
// speedup vs baseline: 1.1525x; 1.0101x over previous
#include <cuda_runtime.h>
#include <cstdint>

#define Bq 16
#define Cq 512
#define Nq 4096
#define Kq 64

typedef unsigned long long ull;

// ================= scratch (static device allocations only) =================
__device__ uint4 gW16[32][512];            // per-16c-chunk fp16 W images (8KB each)
__device__ float gInvS[Kq][Cq];
__device__ float gCst[Kq];
__device__ float g_sa[(size_t)Bq*Kq*Nq];
__device__ uint2 g_sa16b[(size_t)Bq*Kq*256*4]; // hi-only fp16 sa image (8.4MB)
__device__ float g_wsp[Bq][16][Kq];            // per-(b,ntile) wsum partials
__device__ float g_wx8[8][Bq][Kq][Cq];
__device__ float g_row[Bq][Kq];
__device__ float g_nodes[Bq][Kq][Cq];

#define SA_SCALE   2048.0f
#define SA_INV     4.8828125e-4f   // 2^-11

// ================= helpers =================
__device__ __forceinline__ unsigned pk2h(float lo, float hi) {
    unsigned d;
    asm("cvt.rn.f16x2.f32 %0, %1, %2;" : "=r"(d) : "f"(hi), "f"(lo));
    return d;
}
__device__ __forceinline__ float2 unpk2h(unsigned u) {
    float lo, hi;
    asm("{.reg .f16 a,b; mov.b32 {a,b}, %2; cvt.f32.f16 %0, a; cvt.f32.f16 %1, b;}"
        : "=f"(lo), "=f"(hi) : "r"(u));
    return make_float2(lo, hi);
}
// split pair (v0=even slot, v1=odd slot) into fp16x2 hi and lo regs
__device__ __forceinline__ void splitpair(float v0, float v1, unsigned& h, unsigned& l) {
    h = pk2h(v0, v1);
    float2 f = unpk2h(h);
    l = pk2h(v0 - f.x, v1 - f.y);
}
__device__ __forceinline__ void mmaH(float* d, const unsigned* a, const unsigned* b) {
    asm volatile(
        "mma.sync.aligned.m16n8k16.row.col.f32.f16.f16.f32 "
        "{%0,%1,%2,%3}, {%4,%5,%6,%7}, {%8,%9}, {%0,%1,%2,%3};"
        : "+f"(d[0]), "+f"(d[1]), "+f"(d[2]), "+f"(d[3])
        : "r"(a[0]), "r"(a[1]), "r"(a[2]), "r"(a[3]), "r"(b[0]), "r"(b[1]));
}
__device__ __forceinline__ uint32_t smem_u32(const void* p) {
    uint32_t a;
    asm("{ .reg .u64 t; cvta.to.shared.u64 t, %1; cvt.u32.u64 %0, t; }" : "=r"(a) : "l"(p));
    return a;
}
// ---- packed f32x2 ops (proven on this harness in R1/R2) ----
__device__ __forceinline__ ull fma2(ull a, ull b, ull c) {
    ull d; asm("fma.rn.f32x2 %0, %1, %2, %3;" : "=l"(d) : "l"(a), "l"(b), "l"(c)); return d;
}
__device__ __forceinline__ ull add2(ull a, ull b) {
    ull d; asm("add.rn.f32x2 %0, %1, %2;" : "=l"(d) : "l"(a), "l"(b)); return d;
}
__device__ __forceinline__ ull mul2(ull a, ull b) {
    ull d; asm("mul.rn.f32x2 %0, %1, %2;" : "=l"(d) : "l"(a), "l"(b)); return d;
}
__device__ __forceinline__ ull pk2(float v) {
    ull d; unsigned r = __float_as_uint(v);
    asm("mov.b64 %0, {%1, %1};" : "=l"(d) : "r"(r)); return d;
}
__device__ __forceinline__ ull pack2f(float a, float b) {
    ull d; asm("mov.b64 %0, {%1, %2};" : "=l"(d) : "f"(a), "f"(b)); return d;
}
__device__ __forceinline__ ull pack2u(unsigned a, unsigned b) {
    ull d; asm("mov.b64 %0, {%1, %2};" : "=l"(d) : "r"(a), "r"(b)); return d;
}
__device__ __forceinline__ float2 up2(ull a) {
    unsigned x, y;
    asm("mov.b64 {%0, %1}, %2;" : "=r"(x), "=r"(y) : "l"(a));
    return make_float2(__uint_as_float(x), __uint_as_float(y));
}
__device__ __forceinline__ void up2u(ull a, unsigned& x, unsigned& y) {
    asm("mov.b64 {%0, %1}, %2;" : "=r"(x), "=r"(y) : "l"(a));
}
#define CP16(dst, src) asm volatile("cp.async.cg.shared.global [%0], [%1], 16;" :: "r"(dst), "l"(src))
#define CPCOMMIT()     asm volatile("cp.async.commit_group;" ::: "memory")
#define CPWAIT2()      asm volatile("cp.async.wait_group 2;" ::: "memory")
#define CPWAIT1()      asm volatile("cp.async.wait_group 1;" ::: "memory")
#define CPWAIT0()      asm volatile("cp.async.wait_group 0;" ::: "memory")

// ===== phase1: 4 bufs of { A raw x [16c][260f pitch], B fp16 image 8KB } =====
#define P1_BUF   24832u
#define P1_BOFF  16640u
#define P1_SMEM  99328
// ===== phase2: 4 bufs of { A raw x [256c][16n] swizzled 16KB, B hi sa16 2KB } =====
#define P2_BUF   18432u
#define P2_BOFF  16384u
#define P2_SMEM  73728

// ================= prep: sigma, fp16 W images, const =================
__global__ void prep_kernel(const float* __restrict__ anchor,
                            const float* __restrict__ sraw) {
    const int k = blockIdx.x;       // 64
    const int tid = threadIdx.x;    // 256
    float part = 0.f;
#pragma unroll
    for (int jj = 0; jj < 2; ++jj) {
        int c = tid + jj * 256;
        float sr = sraw[k * Cq + c];
        float sg = 1.f / (1.f + __expf(-sr));
        float a  = anchor[k * Cq + c];
        float i2 = 1.f / (sg * sg);
        float w2 = -2.f * a * i2;
        gInvS[k][c] = 1.f / sg;
        part += a * a * i2;
        int ch = c >> 4, cl = c & 15;
        int j = k >> 3, gg = k & 7;
        int q = (cl >> 1) & 3, reg = cl >> 3, half = cl & 1;
        float vals[2] = { i2, w2 };   // step0 = x^2 weight, step1 = x weight
#pragma unroll
        for (int s = 0; s < 2; ++s) {
            unsigned hp, lp;
            splitpair(vals[s], 0.f, hp, lp);
            unsigned short* base =
                (unsigned short*)&gW16[ch][(((s * 8 + j) * 8 + gg) * 4 + q)];
            base[reg * 2 + half]     = (unsigned short)(hp & 0xFFFFu);
            base[4 + reg * 2 + half] = (unsigned short)(lp & 0xFFFFu);
        }
    }
#pragma unroll
    for (int off = 16; off; off >>= 1) part += __shfl_xor_sync(0xffffffffu, part, off);
    __shared__ float red[8];
    if ((tid & 31) == 0) red[tid >> 5] = part;
    __syncthreads();
    if (tid == 0) {
        float s = 0.f;
#pragma unroll
        for (int i = 0; i < 8; ++i) s += red[i];
        gCst[k] = s;
    }
}

// ================= phase 1: distance GEMM (3xFP16 mma) + hybrid-exp softmax
//                   + fused sa16/wsum emission. 4-stage cp.async pipeline. =====
__global__ __launch_bounds__(256, 2)
void phase1_kernel(const float* __restrict__ x, float* __restrict__ sa) {
    extern __shared__ char smem[];
    __shared__ float cst[64];
    const uint32_t sb = smem_u32(smem);
    const int tid = threadIdx.x;
    const int w = tid >> 5, lane = tid & 31;
    const int g = lane >> 2, q = lane & 3;
    const int n0w = w << 5;
    const int b  = blockIdx.y;
    const int ntile = blockIdx.x;
    const int n0 = ntile << 8;
    const float* xb = x + (size_t)b * Cq * Nq + n0;
    if (tid < 64) cst[tid] = gCst[tid];

    float acc[2][8][4];
#pragma unroll
    for (int i = 0; i < 2; ++i)
#pragma unroll
        for (int j = 0; j < 8; ++j)
#pragma unroll
            for (int e = 0; e < 4; ++e) acc[i][j][e] = 0.f;

    auto fill = [&](int ch) {
        const uint32_t base = sb + (uint32_t)(ch & 3) * P1_BUF;
        const float* xc = xb + (size_t)(ch << 4) * Nq;
#pragma unroll
        for (int it = 0; it < 4; ++it) {
            int u = tid + (it << 8);
            int row = u >> 6, seg = u & 63;
            CP16(base + (uint32_t)row * 1040u + (uint32_t)(seg << 4),
                 xc + (size_t)row * Nq + (seg << 2));
        }
#pragma unroll
        for (int it = 0; it < 2; ++it) {
            int u = tid + (it << 8);
            CP16(base + P1_BOFF + (uint32_t)(u << 4), &gW16[ch][u]);
        }
        CPCOMMIT();
    };

    auto gemm = [&](int buf) {
        const float* fA = (const float*)(smem + (uint32_t)buf * P1_BUF);
        const uint4* fB = (const uint4*)(smem + (uint32_t)buf * P1_BUF + P1_BOFF);
        float xv[2][8];
#pragma unroll
        for (int i = 0; i < 2; ++i) {
            const float* pa = fA + n0w + (i << 4) + g;
            xv[i][0] = pa[(2 * q) * 260];         xv[i][1] = pa[(2 * q + 1) * 260];
            xv[i][2] = pa[(2 * q + 8) * 260];     xv[i][3] = pa[(2 * q + 9) * 260];
            xv[i][4] = pa[(2 * q) * 260 + 8];     xv[i][5] = pa[(2 * q + 1) * 260 + 8];
            xv[i][6] = pa[(2 * q + 8) * 260 + 8]; xv[i][7] = pa[(2 * q + 9) * 260 + 8];
        }
#pragma unroll
        for (int s = 0; s < 2; ++s) {
            unsigned aH[2][4], aL[2][4];
#pragma unroll
            for (int i = 0; i < 2; ++i) {
                float e0, e1, e2, e3, e4, e5, e6, e7;
                if (s == 0) {
                    e0 = xv[i][0] * xv[i][0]; e1 = xv[i][1] * xv[i][1];
                    e2 = xv[i][2] * xv[i][2]; e3 = xv[i][3] * xv[i][3];
                    e4 = xv[i][4] * xv[i][4]; e5 = xv[i][5] * xv[i][5];
                    e6 = xv[i][6] * xv[i][6]; e7 = xv[i][7] * xv[i][7];
                } else {
                    e0 = xv[i][0]; e1 = xv[i][1]; e2 = xv[i][2]; e3 = xv[i][3];
                    e4 = xv[i][4]; e5 = xv[i][5]; e6 = xv[i][6]; e7 = xv[i][7];
                }
                splitpair(e0, e1, aH[i][0], aL[i][0]);
                splitpair(e4, e5, aH[i][1], aL[i][1]);
                splitpair(e2, e3, aH[i][2], aL[i][2]);
                splitpair(e6, e7, aH[i][3], aL[i][3]);
            }
#pragma unroll
            for (int jb = 0; jb < 2; ++jb) {
                uint4 w4[4];
#pragma unroll
                for (int jj = 0; jj < 4; ++jj)
                    w4[jj] = fB[(((s * 8 + (jb << 2) + jj) * 8 + g) << 2) + q];
#pragma unroll
                for (int jj = 0; jj < 4; ++jj) {
                    unsigned bh[2] = { w4[jj].x, w4[jj].y };
                    mmaH(acc[0][(jb << 2) + jj], aH[0], bh);
                    mmaH(acc[1][(jb << 2) + jj], aH[1], bh);
                }
#pragma unroll
                for (int jj = 0; jj < 4; ++jj) {
                    unsigned bl[2] = { w4[jj].z, w4[jj].w };
                    mmaH(acc[0][(jb << 2) + jj], aH[0], bl);
                    mmaH(acc[1][(jb << 2) + jj], aH[1], bl);
                }
#pragma unroll
                for (int jj = 0; jj < 4; ++jj) {
                    unsigned bh[2] = { w4[jj].x, w4[jj].y };
                    mmaH(acc[0][(jb << 2) + jj], aL[0], bh);
                    mmaH(acc[1][(jb << 2) + jj], aL[1], bh);
                }
            }
        }
    };

    fill(0); fill(1); fill(2);
    for (int ch = 0; ch < 32; ++ch) {
        if (ch + 2 < 32) { CPWAIT2(); } else if (ch + 1 < 32) { CPWAIT1(); } else { CPWAIT0(); }
        __syncthreads();
        if (ch + 3 < 32) fill(ch + 3);
        gemm(ch & 3);
    }
    CPWAIT0();
    __syncthreads();

    // stage d2 in smem (overlays buffers)
    float* d2 = (float*)smem;
#pragma unroll
    for (int i = 0; i < 2; ++i) {
        int r0 = n0w + (i << 4) + g;
#pragma unroll
        for (int j = 0; j < 8; ++j) {
            int kc = (j << 3) + (q << 1);
            *(float2*)&d2[r0 * 66 + kc]       = make_float2(acc[i][j][0], acc[i][j][1]);
            *(float2*)&d2[(r0 + 8) * 66 + kc] = make_float2(acc[i][j][2], acc[i][j][3]);
        }
    }
    __syncthreads();

    // softmax: one thread per n. Hybrid exp: k<40 MUFU, k>=40 packed-FMA poly.
    float e[64];
    {
#pragma unroll
        for (int k = 0; k < 64; ++k) e[k] = d2[tid * 66 + k] + cst[k];
        float mn = e[0];
#pragma unroll
        for (int k = 1; k < 64; ++k) mn = fminf(mn, e[k]);
        float s = 0.f;
#pragma unroll
        for (int k = 0; k < 40; ++k) {
            float t = __expf(-0.5f * (e[k] - mn));
            e[k] = t;
            s += t;
        }
        // packed exp2 poly: u = (mn - e)*0.5*log2e; p = 2^u
        const float Cc = -0.72134752044f;          // -0.5*log2(e)
        const ull C2 = pk2(Cc);
        const ull MN2 = pk2(-mn * Cc);
        const ull MG2 = pk2(12582912.0f);          // 1.5*2^23
        const ull NMG2 = pk2(-12582912.0f);
#pragma unroll
        for (int kp = 40; kp < 64; kp += 2) {
            ull e2 = pack2f(e[kp], e[kp + 1]);
            ull u2 = fma2(e2, C2, MN2);            // (e-mn)*Cc  (<= 0)
            ull y2 = add2(u2, MG2);                // magic round
            ull t2 = add2(y2, NMG2);               // n as float
            ull r2 = fma2(t2, pk2(-1.0f), u2);     // r = u - n, in [-0.5,0.5]
            unsigned ylo, yhi;
            up2u(y2, ylo, yhi);
            int n0i = (int)(ylo - 0x4B400000u); if (n0i < -126) n0i = -126;
            int n1i = (int)(yhi - 0x4B400000u); if (n1i < -126) n1i = -126;
            unsigned sc0 = (unsigned)(n0i + 127) << 23;
            unsigned sc1 = (unsigned)(n1i + 127) << 23;
            ull sc2 = pack2u(sc0, sc1);
            ull P = pk2(0.0013333558f);
            P = fma2(P, r2, pk2(0.0096181291f));
            P = fma2(P, r2, pk2(0.0555041090f));
            P = fma2(P, r2, pk2(0.2402265100f));
            P = fma2(P, r2, pk2(0.6931471800f));
            P = fma2(P, r2, pk2(1.0f));
            ull p2 = mul2(P, sc2);
            float2 pv = up2(p2);
            e[kp] = pv.x; e[kp + 1] = pv.y;
            s += pv.x;
            s += pv.y;
        }
        float r = 1.f / s;
#pragma unroll
        for (int k = 0; k < 64; ++k) e[k] *= r;
    }
    __syncthreads();   // all d2 reads done before overwrite

    // transpose p into [k][256] (pitch 264), write sa fp32
    float* psh = (float*)smem;
#pragma unroll
    for (int k = 0; k < 64; ++k) psh[k * 264 + tid] = e[k];
    {
        float* sp = sa + (size_t)b * Kq * Nq + n0 + tid;
#pragma unroll
        for (int k = 0; k < 64; ++k) sp[(size_t)k * Nq] = e[k];
    }
    __syncthreads();

    // build hi-only fp16 sa image + wsum partials. unit u = (k, ch16)
    float* wssh = (float*)(smem + 67584);
#pragma unroll
    for (int it = 0; it < 4; ++it) {
        int u = tid + (it << 8);
        int k = u >> 4, ch = u & 15;
        const float* src = psh + k * 264 + (ch << 4);
        float4 v0 = *(const float4*)(src);
        float4 v1 = *(const float4*)(src + 4);
        float4 v2 = *(const float4*)(src + 8);
        float4 v3 = *(const float4*)(src + 12);
        uint4 oA, oB;
        oA.x = pk2h(v0.x * SA_SCALE, v0.y * SA_SCALE);
        oA.y = pk2h(v2.x * SA_SCALE, v2.y * SA_SCALE);
        oA.z = pk2h(v0.z * SA_SCALE, v0.w * SA_SCALE);
        oA.w = pk2h(v2.z * SA_SCALE, v2.w * SA_SCALE);
        oB.x = pk2h(v1.x * SA_SCALE, v1.y * SA_SCALE);
        oB.y = pk2h(v3.x * SA_SCALE, v3.y * SA_SCALE);
        oB.z = pk2h(v1.z * SA_SCALE, v1.w * SA_SCALE);
        oB.w = pk2h(v3.z * SA_SCALE, v3.w * SA_SCALE);
        size_t dstbase = ((size_t)((b * 64 + k) * 256 + (ntile << 4) + ch)) << 2;
        *(uint4*)&g_sa16b[dstbase]     = oA;   // qq 0,1
        *(uint4*)&g_sa16b[dstbase + 2] = oB;   // qq 2,3
        float sA = ((v0.x + v0.y) + (v0.z + v0.w)) + ((v1.x + v1.y) + (v1.z + v1.w));
        float sB = ((v2.x + v2.y) + (v2.z + v2.w)) + ((v3.x + v3.y) + (v3.z + v3.w));
        wssh[u] = sA + sB;
    }
    __syncthreads();
    if (tid < 64) {
        float s = 0.f;
#pragma unroll
        for (int c = 0; c < 16; ++c) s += wssh[tid * 16 + c];
        g_wsp[b][ntile][tid] = s;
    }
}

// ================= phase 2: wx[c,k] = sum_n x[c,n]*sa16[k,n]  (1-pass fp16) =====
__global__ __launch_bounds__(256, 2)
void phase2_kernel(const float* __restrict__ x) {
    extern __shared__ char smem[];
    const uint32_t sb = smem_u32(smem);
    const int tid = threadIdx.x;
    const int w = tid >> 5, lane = tid & 31;
    const int g = lane >> 2, q = lane & 3;
    const int c0w = w << 5;
    const int c0 = (int)blockIdx.x << 8;
    const int b  = blockIdx.y;
    const int seg = blockIdx.z;
    const int n0 = seg << 9;
    const float* xb = x + ((size_t)b * Cq + c0) * Nq + n0;

    float acc[2][8][4];
#pragma unroll
    for (int i = 0; i < 2; ++i)
#pragma unroll
        for (int j = 0; j < 8; ++j)
#pragma unroll
            for (int e = 0; e < 4; ++e) acc[i][j][e] = 0.f;

    auto fill = [&](int ch) {
        const uint32_t base = sb + (uint32_t)(ch & 3) * P2_BUF;
        const int nn = ch << 4;
#pragma unroll
        for (int it = 0; it < 4; ++it) {
            int u = tid + (it << 8);
            int row = u >> 2, sg2 = u & 3;
            CP16(base + (uint32_t)(row << 6) + (uint32_t)((sg2 ^ ((row >> 1) & 3)) << 4),
                 xb + (size_t)row * Nq + nn + (sg2 << 2));
        }
        if (tid < 128) {
            int node = tid >> 1, qq2 = tid & 1;
            CP16(base + P2_BOFF + (uint32_t)(tid << 4),
                 &g_sa16b[(((size_t)((b * 64 + node) * 256 + (seg << 5) + ch)) << 2) + (qq2 << 1)]);
        }
        CPCOMMIT();
    };

    auto gemm = [&](int buf) {
        const float* fA = (const float*)(smem + (uint32_t)buf * P2_BUF);
        const uint2* fB = (const uint2*)(smem + (uint32_t)buf * P2_BUF + P2_BOFF);
        unsigned aH[2][4];
#pragma unroll
        for (int i = 0; i < 2; ++i) {
            int r0 = c0w + (i << 4) + g;
            int r1 = r0 + 8;
            int k0 = ((r0 >> 1) & 3) << 2;
            int k1 = ((r1 >> 1) & 3) << 2;
            float2 p00 = *(const float2*)(fA + (r0 << 4) + ((2 * q) ^ k0));
            float2 p01 = *(const float2*)(fA + (r0 << 4) + ((2 * q + 8) ^ k0));
            float2 p10 = *(const float2*)(fA + (r1 << 4) + ((2 * q) ^ k1));
            float2 p11 = *(const float2*)(fA + (r1 << 4) + ((2 * q + 8) ^ k1));
            aH[i][0] = pk2h(p00.x, p00.y);
            aH[i][1] = pk2h(p10.x, p10.y);
            aH[i][2] = pk2h(p01.x, p01.y);
            aH[i][3] = pk2h(p11.x, p11.y);
        }
#pragma unroll
        for (int jb = 0; jb < 2; ++jb) {
            uint2 w2[4];
#pragma unroll
            for (int jj = 0; jj < 4; ++jj)
                w2[jj] = fB[(((((jb << 2) + jj) << 3) + g) << 2) + q];
#pragma unroll
            for (int jj = 0; jj < 4; ++jj) {
                unsigned bh[2] = { w2[jj].x, w2[jj].y };
                mmaH(acc[0][(jb << 2) + jj], aH[0], bh);
                mmaH(acc[1][(jb << 2) + jj], aH[1], bh);
            }
        }
    };

    fill(0); fill(1); fill(2);
    for (int ch = 0; ch < 32; ++ch) {
        if (ch + 2 < 32) { CPWAIT2(); } else if (ch + 1 < 32) { CPWAIT1(); } else { CPWAIT0(); }
        __syncthreads();
        if (ch + 3 < 32) fill(ch + 3);
        gemm(ch & 3);
    }

    // epilogue: unscale by 2^-11, scatter D[c,k] partials
    float* basep = &g_wx8[seg][b][0][0];
#pragma unroll
    for (int j = 0; j < 8; ++j) {
        int kc = (j << 3) + (q << 1);
#pragma unroll
        for (int i = 0; i < 2; ++i) {
            int cc = c0 + c0w + (i << 4) + g;
            basep[(size_t)kc * Cq + cc]           = acc[i][j][0] * SA_INV;
            basep[(size_t)(kc + 1) * Cq + cc]     = acc[i][j][1] * SA_INV;
            basep[(size_t)kc * Cq + cc + 8]       = acc[i][j][2] * SA_INV;
            basep[(size_t)(kc + 1) * Cq + cc + 8] = acc[i][j][3] * SA_INV;
        }
    }
}

// ================= phase 3: nodes + per-row l2norm =================
__global__ void phase3_kernel(const float* __restrict__ anchor) {
    const int bk = blockIdx.x;     // 1024
    const int b = bk >> 6, k = bk & 63;
    const int tid = threadIdx.x;   // 128
    float wsv = 0.f;
#pragma unroll
    for (int t = 0; t < 16; ++t) wsv += g_wsp[b][t][k];
    const float invw = 1.f / (wsv + 1e-9f);
    float t4[4];
    float ssq = 0.f;
#pragma unroll
    for (int j = 0; j < 4; ++j) {
        int c = tid + j * 128;
        float wx = 0.f;
#pragma unroll
        for (int s = 0; s < 8; ++s) wx += g_wx8[s][b][k][c];
        float nd = (wx - wsv * anchor[k * Cq + c]) * gInvS[k][c] * invw;
        t4[j] = nd;
        ssq += nd * nd;
    }
#pragma unroll
    for (int off = 16; off; off >>= 1) ssq += __shfl_xor_sync(0xffffffffu, ssq, off);
    __shared__ float red[4];
    __shared__ float totsh;
    if ((tid & 31) == 0) red[tid >> 5] = ssq;
    __syncthreads();
    if (tid == 0) totsh = red[0] + red[1] + red[2] + red[3];
    __syncthreads();
    float total = totsh;
    float scale = 1.f / fmaxf(sqrtf(total), 1e-12f);
#pragma unroll
    for (int j = 0; j < 4; ++j) {
        int c = tid + j * 128;
        g_nodes[b][k][c] = t4[j] * scale;
    }
    if (tid == 0) g_row[b][k] = total * scale * scale;
}

// ================= phase 4: global l2norm + output =================
__global__ void phase4_kernel(float* __restrict__ outflat) {
    const int b = blockIdx.x;      // 16
    const int tid = threadIdx.x;   // 256
    __shared__ float red[64];
    __shared__ float gsh;
    if (tid < 64) red[tid] = g_row[b][tid];
    __syncthreads();
    if (tid == 0) {
        float s = 0.f;
#pragma unroll
        for (int i = 0; i < 64; ++i) s += red[i];
        gsh = 1.f / fmaxf(sqrtf(s), 1e-12f);
    }
    __syncthreads();
    float g = gsh;
    const float* np = &g_nodes[b][0][0];
    float* op = outflat + (size_t)b * Kq * Cq;
    for (int i = tid; i < Kq * Cq; i += 256) op[i] = np[i] * g;
}

// ================= launch =================
extern "C" void kernel_launch(void* const* d_in, const int* in_sizes, int n_in,
                              void* d_out, int out_size) {
    const float* x      = (const float*)d_in[0];
    const float* anchor = (const float*)d_in[1];
    const float* sraw   = (const float*)d_in[2];
    float* outf = (float*)d_out;

    const int FLAT = Bq * Cq * Kq;      // 524288
    const int SA   = Bq * Kq * Nq;      // 4194304

    float* sa_dev = nullptr;
    cudaGetSymbolAddress((void**)&sa_dev, g_sa);
    float* nodes_dev = nullptr;
    cudaGetSymbolAddress((void**)&nodes_dev, g_nodes);

    float* sa_ptr;
    float* flat_ptr;
    if (out_size == FLAT) {
        flat_ptr = outf;
        sa_ptr = sa_dev;
    } else if (out_size == SA) {
        sa_ptr = outf;
        flat_ptr = nodes_dev;
    } else {
        flat_ptr = outf;
        sa_ptr = outf + FLAT;
    }

    static bool attr_done = false;
    if (!attr_done) {
        cudaFuncSetAttribute(phase1_kernel,
                             cudaFuncAttributeMaxDynamicSharedMemorySize, P1_SMEM);
        cudaFuncSetAttribute(phase2_kernel,
                             cudaFuncAttributeMaxDynamicSharedMemorySize, P2_SMEM);
        attr_done = true;
    }

    prep_kernel<<<Kq, 256>>>(anchor, sraw);
    phase1_kernel<<<dim3(Nq / 256, Bq), 256, P1_SMEM>>>(x, sa_ptr);
    phase2_kernel<<<dim3(Cq / 256, Bq, 8), 256, P2_SMEM>>>(x);
    phase3_kernel<<<Bq * Kq, 128>>>(anchor);
    phase4_kernel<<<Bq, 256>>>(flat_ptr);
}

// round 17
// speedup vs baseline: 1.3237x; 1.1485x over previous
#include <cuda_runtime.h>
#include <cstdint>

#define Bq 16
#define Cq 512
#define Nq 4096
#define Kq 64

typedef unsigned long long ull;

// ================= scratch (static device allocations only) =================
__device__ uint4 gW16[32][512];            // per-16c-chunk fp16 W images (8KB each)
__device__ float gInvS[Kq][Cq];
__device__ float gCst[Kq];
__device__ float g_sa[(size_t)Bq*Kq*Nq];
__device__ uint2 g_sa16b[(size_t)Bq*Kq*256*4]; // hi-only fp16 sa image (8.4MB)
__device__ float g_wsp[Bq][16][Kq];            // per-(b,ntile) wsum partials
__device__ float g_wx8[8][Bq][Kq][Cq];
__device__ float g_row[Bq][Kq];
__device__ float g_nodes[Bq][Kq][Cq];

#define SA_SCALE   2048.0f
#define SA_INV     4.8828125e-4f   // 2^-11

// ================= helpers =================
__device__ __forceinline__ unsigned pk2h(float lo, float hi) {
    unsigned d;
    asm("cvt.rn.f16x2.f32 %0, %1, %2;" : "=r"(d) : "f"(hi), "f"(lo));
    return d;
}
__device__ __forceinline__ float2 unpk2h(unsigned u) {
    float lo, hi;
    asm("{.reg .f16 a,b; mov.b32 {a,b}, %2; cvt.f32.f16 %0, a; cvt.f32.f16 %1, b;}"
        : "=f"(lo), "=f"(hi) : "r"(u));
    return make_float2(lo, hi);
}
// split pair (v0=even slot, v1=odd slot) into fp16x2 hi and lo regs
__device__ __forceinline__ void splitpair(float v0, float v1, unsigned& h, unsigned& l) {
    h = pk2h(v0, v1);
    float2 f = unpk2h(h);
    l = pk2h(v0 - f.x, v1 - f.y);
}
__device__ __forceinline__ void mmaH(float* d, const unsigned* a, const unsigned* b) {
    asm volatile(
        "mma.sync.aligned.m16n8k16.row.col.f32.f16.f16.f32 "
        "{%0,%1,%2,%3}, {%4,%5,%6,%7}, {%8,%9}, {%0,%1,%2,%3};"
        : "+f"(d[0]), "+f"(d[1]), "+f"(d[2]), "+f"(d[3])
        : "r"(a[0]), "r"(a[1]), "r"(a[2]), "r"(a[3]), "r"(b[0]), "r"(b[1]));
}
__device__ __forceinline__ uint32_t smem_u32(const void* p) {
    uint32_t a;
    asm("{ .reg .u64 t; cvta.to.shared.u64 t, %1; cvt.u32.u64 %0, t; }" : "=r"(a) : "l"(p));
    return a;
}
// ---- packed f32x2 ops ----
__device__ __forceinline__ ull fma2(ull a, ull b, ull c) {
    ull d; asm("fma.rn.f32x2 %0, %1, %2, %3;" : "=l"(d) : "l"(a), "l"(b), "l"(c)); return d;
}
__device__ __forceinline__ ull add2(ull a, ull b) {
    ull d; asm("add.rn.f32x2 %0, %1, %2;" : "=l"(d) : "l"(a), "l"(b)); return d;
}
__device__ __forceinline__ ull mul2(ull a, ull b) {
    ull d; asm("mul.rn.f32x2 %0, %1, %2;" : "=l"(d) : "l"(a), "l"(b)); return d;
}
__device__ __forceinline__ ull pk2(float v) {
    ull d; unsigned r = __float_as_uint(v);
    asm("mov.b64 %0, {%1, %1};" : "=l"(d) : "r"(r)); return d;
}
__device__ __forceinline__ ull pack2f(float a, float b) {
    ull d; asm("mov.b64 %0, {%1, %2};" : "=l"(d) : "f"(a), "f"(b)); return d;
}
__device__ __forceinline__ ull pack2u(unsigned a, unsigned b) {
    ull d; asm("mov.b64 %0, {%1, %2};" : "=l"(d) : "r"(a), "r"(b)); return d;
}
__device__ __forceinline__ float2 up2(ull a) {
    unsigned x, y;
    asm("mov.b64 {%0, %1}, %2;" : "=r"(x), "=r"(y) : "l"(a));
    return make_float2(__uint_as_float(x), __uint_as_float(y));
}
__device__ __forceinline__ void up2u(ull a, unsigned& x, unsigned& y) {
    asm("mov.b64 {%0, %1}, %2;" : "=r"(x), "=r"(y) : "l"(a));
}
#define CP16(dst, src) asm volatile("cp.async.cg.shared.global [%0], [%1], 16;" :: "r"(dst), "l"(src))
#define CPCOMMIT()     asm volatile("cp.async.commit_group;" ::: "memory")
#define CPWAIT2()      asm volatile("cp.async.wait_group 2;" ::: "memory")
#define CPWAIT1()      asm volatile("cp.async.wait_group 1;" ::: "memory")
#define CPWAIT0()      asm volatile("cp.async.wait_group 0;" ::: "memory")

// ===== phase1: 4 bufs of { A raw x [16c][260f pitch], B fp16 image 8KB } =====
#define P1_BUF   24832u
#define P1_BOFF  16640u
#define P1_SMEM  99328
// ===== phase2: 4 bufs of { A raw x [256c][16n] swizzled 16KB, B hi sa16 2KB } =====
#define P2_BUF   18432u
#define P2_BOFF  16384u
#define P2_SMEM  73728

// ================= prep: sigma, fp16 W images, const =================
__global__ void prep_kernel(const float* __restrict__ anchor,
                            const float* __restrict__ sraw) {
    const int k = blockIdx.x;       // 64
    const int tid = threadIdx.x;    // 256
    float part = 0.f;
#pragma unroll
    for (int jj = 0; jj < 2; ++jj) {
        int c = tid + jj * 256;
        float sr = sraw[k * Cq + c];
        float sg = 1.f / (1.f + __expf(-sr));
        float a  = anchor[k * Cq + c];
        float i2 = 1.f / (sg * sg);
        float w2 = -2.f * a * i2;
        gInvS[k][c] = 1.f / sg;
        part += a * a * i2;
        int ch = c >> 4, cl = c & 15;
        int j = k >> 3, gg = k & 7;
        int q = (cl >> 1) & 3, reg = cl >> 3, half = cl & 1;
        float vals[2] = { i2, w2 };   // step0 = x^2 weight, step1 = x weight
#pragma unroll
        for (int s = 0; s < 2; ++s) {
            unsigned hp, lp;
            splitpair(vals[s], 0.f, hp, lp);
            unsigned short* base =
                (unsigned short*)&gW16[ch][(((s * 8 + j) * 8 + gg) * 4 + q)];
            base[reg * 2 + half]     = (unsigned short)(hp & 0xFFFFu);
            base[4 + reg * 2 + half] = (unsigned short)(lp & 0xFFFFu);
        }
    }
#pragma unroll
    for (int off = 16; off; off >>= 1) part += __shfl_xor_sync(0xffffffffu, part, off);
    __shared__ float red[8];
    if ((tid & 31) == 0) red[tid >> 5] = part;
    __syncthreads();
    if (tid == 0) {
        float s = 0.f;
#pragma unroll
        for (int i = 0; i < 8; ++i) s += red[i];
        gCst[k] = s;
    }
}

// ================= phase 1: distance GEMM (3xFP16 mma) + hybrid-exp softmax
//                   + fused vectorized sa/sa16/wsum emission. =================
__global__ __launch_bounds__(256, 2)
void phase1_kernel(const float* __restrict__ x, float* __restrict__ sa) {
    extern __shared__ char smem[];
    __shared__ float cst[64];
    const uint32_t sb = smem_u32(smem);
    const int tid = threadIdx.x;
    const int w = tid >> 5, lane = tid & 31;
    const int g = lane >> 2, q = lane & 3;
    const int n0w = w << 5;
    const int b  = blockIdx.y;
    const int ntile = blockIdx.x;
    const int n0 = ntile << 8;
    const float* xb = x + (size_t)b * Cq * Nq + n0;
    if (tid < 64) cst[tid] = gCst[tid];

    float acc[2][8][4];
#pragma unroll
    for (int i = 0; i < 2; ++i)
#pragma unroll
        for (int j = 0; j < 8; ++j)
#pragma unroll
            for (int e = 0; e < 4; ++e) acc[i][j][e] = 0.f;

    auto fill = [&](int ch) {
        const uint32_t base = sb + (uint32_t)(ch & 3) * P1_BUF;
        const float* xc = xb + (size_t)(ch << 4) * Nq;
#pragma unroll
        for (int it = 0; it < 4; ++it) {
            int u = tid + (it << 8);
            int row = u >> 6, seg = u & 63;
            CP16(base + (uint32_t)row * 1040u + (uint32_t)(seg << 4),
                 xc + (size_t)row * Nq + (seg << 2));
        }
#pragma unroll
        for (int it = 0; it < 2; ++it) {
            int u = tid + (it << 8);
            CP16(base + P1_BOFF + (uint32_t)(u << 4), &gW16[ch][u]);
        }
        CPCOMMIT();
    };

    auto gemm = [&](int buf) {
        const float* fA = (const float*)(smem + (uint32_t)buf * P1_BUF);
        const uint4* fB = (const uint4*)(smem + (uint32_t)buf * P1_BUF + P1_BOFF);
        float xv[2][8];
#pragma unroll
        for (int i = 0; i < 2; ++i) {
            const float* pa = fA + n0w + (i << 4) + g;
            xv[i][0] = pa[(2 * q) * 260];         xv[i][1] = pa[(2 * q + 1) * 260];
            xv[i][2] = pa[(2 * q + 8) * 260];     xv[i][3] = pa[(2 * q + 9) * 260];
            xv[i][4] = pa[(2 * q) * 260 + 8];     xv[i][5] = pa[(2 * q + 1) * 260 + 8];
            xv[i][6] = pa[(2 * q + 8) * 260 + 8]; xv[i][7] = pa[(2 * q + 9) * 260 + 8];
        }
#pragma unroll
        for (int s = 0; s < 2; ++s) {
            unsigned aH[2][4], aL[2][4];
#pragma unroll
            for (int i = 0; i < 2; ++i) {
                float e0, e1, e2, e3, e4, e5, e6, e7;
                if (s == 0) {
                    e0 = xv[i][0] * xv[i][0]; e1 = xv[i][1] * xv[i][1];
                    e2 = xv[i][2] * xv[i][2]; e3 = xv[i][3] * xv[i][3];
                    e4 = xv[i][4] * xv[i][4]; e5 = xv[i][5] * xv[i][5];
                    e6 = xv[i][6] * xv[i][6]; e7 = xv[i][7] * xv[i][7];
                } else {
                    e0 = xv[i][0]; e1 = xv[i][1]; e2 = xv[i][2]; e3 = xv[i][3];
                    e4 = xv[i][4]; e5 = xv[i][5]; e6 = xv[i][6]; e7 = xv[i][7];
                }
                splitpair(e0, e1, aH[i][0], aL[i][0]);
                splitpair(e4, e5, aH[i][1], aL[i][1]);
                splitpair(e2, e3, aH[i][2], aL[i][2]);
                splitpair(e6, e7, aH[i][3], aL[i][3]);
            }
#pragma unroll
            for (int jb = 0; jb < 2; ++jb) {
                uint4 w4[4];
#pragma unroll
                for (int jj = 0; jj < 4; ++jj)
                    w4[jj] = fB[(((s * 8 + (jb << 2) + jj) * 8 + g) << 2) + q];
#pragma unroll
                for (int jj = 0; jj < 4; ++jj) {
                    unsigned bh[2] = { w4[jj].x, w4[jj].y };
                    mmaH(acc[0][(jb << 2) + jj], aH[0], bh);
                    mmaH(acc[1][(jb << 2) + jj], aH[1], bh);
                }
#pragma unroll
                for (int jj = 0; jj < 4; ++jj) {
                    unsigned bl[2] = { w4[jj].z, w4[jj].w };
                    mmaH(acc[0][(jb << 2) + jj], aH[0], bl);
                    mmaH(acc[1][(jb << 2) + jj], aH[1], bl);
                }
#pragma unroll
                for (int jj = 0; jj < 4; ++jj) {
                    unsigned bh[2] = { w4[jj].x, w4[jj].y };
                    mmaH(acc[0][(jb << 2) + jj], aL[0], bh);
                    mmaH(acc[1][(jb << 2) + jj], aL[1], bh);
                }
            }
        }
    };

    fill(0); fill(1); fill(2);
    for (int ch = 0; ch < 32; ++ch) {
        if (ch + 2 < 32) { CPWAIT2(); } else if (ch + 1 < 32) { CPWAIT1(); } else { CPWAIT0(); }
        __syncthreads();
        if (ch + 3 < 32) fill(ch + 3);
        gemm(ch & 3);
    }
    CPWAIT0();
    __syncthreads();

    // stage d2 in smem (overlays buffers)
    float* d2 = (float*)smem;
#pragma unroll
    for (int i = 0; i < 2; ++i) {
        int r0 = n0w + (i << 4) + g;
#pragma unroll
        for (int j = 0; j < 8; ++j) {
            int kc = (j << 3) + (q << 1);
            *(float2*)&d2[r0 * 66 + kc]       = make_float2(acc[i][j][0], acc[i][j][1]);
            *(float2*)&d2[(r0 + 8) * 66 + kc] = make_float2(acc[i][j][2], acc[i][j][3]);
        }
    }
    __syncthreads();

    // softmax: one thread per n. Hybrid exp: k<40 MUFU, k>=40 packed-FMA poly.
    float e[64];
    {
#pragma unroll
        for (int k = 0; k < 64; ++k) e[k] = d2[tid * 66 + k] + cst[k];
        float mn = e[0];
#pragma unroll
        for (int k = 1; k < 64; ++k) mn = fminf(mn, e[k]);
        float s = 0.f;
#pragma unroll
        for (int k = 0; k < 40; ++k) {
            float t = __expf(-0.5f * (e[k] - mn));
            e[k] = t;
            s += t;
        }
        const float Cc = -0.72134752044f;          // -0.5*log2(e)
        const ull C2 = pk2(Cc);
        const ull MN2 = pk2(-mn * Cc);
        const ull MG2 = pk2(12582912.0f);          // 1.5*2^23
        const ull NMG2 = pk2(-12582912.0f);
#pragma unroll
        for (int kp = 40; kp < 64; kp += 2) {
            ull e2 = pack2f(e[kp], e[kp + 1]);
            ull u2 = fma2(e2, C2, MN2);            // (e-mn)*Cc  (<= 0)
            ull y2 = add2(u2, MG2);                // magic round
            ull t2 = add2(y2, NMG2);               // n as float
            ull r2 = fma2(t2, pk2(-1.0f), u2);     // r = u - n, in [-0.5,0.5]
            unsigned ylo, yhi;
            up2u(y2, ylo, yhi);
            int n0i = (int)(ylo - 0x4B400000u); if (n0i < -126) n0i = -126;
            int n1i = (int)(yhi - 0x4B400000u); if (n1i < -126) n1i = -126;
            unsigned sc0 = (unsigned)(n0i + 127) << 23;
            unsigned sc1 = (unsigned)(n1i + 127) << 23;
            ull sc2 = pack2u(sc0, sc1);
            ull P = pk2(0.0013333558f);
            P = fma2(P, r2, pk2(0.0096181291f));
            P = fma2(P, r2, pk2(0.0555041090f));
            P = fma2(P, r2, pk2(0.2402265100f));
            P = fma2(P, r2, pk2(0.6931471800f));
            P = fma2(P, r2, pk2(1.0f));
            ull p2 = mul2(P, sc2);
            float2 pv = up2(p2);
            e[kp] = pv.x; e[kp + 1] = pv.y;
            s += pv.x;
            s += pv.y;
        }
        float r = 1.f / s;
#pragma unroll
        for (int k = 0; k < 64; ++k) e[k] *= r;
    }
    __syncthreads();   // all d2 reads done before overwrite

    // transpose p into [k][256] (pitch 264)
    float* psh = (float*)smem;
#pragma unroll
    for (int k = 0; k < 64; ++k) psh[k * 264 + tid] = e[k];
    __syncthreads();

    // vectorized: fp32 sa stores + hi-only fp16 sa image + wsum partials.
    float* wssh = (float*)(smem + 67584);
#pragma unroll
    for (int it = 0; it < 4; ++it) {
        int u = tid + (it << 8);
        int k = u >> 4, ch = u & 15;
        const float* src = psh + k * 264 + (ch << 4);
        float4 v0 = *(const float4*)(src);
        float4 v1 = *(const float4*)(src + 4);
        float4 v2 = *(const float4*)(src + 8);
        float4 v3 = *(const float4*)(src + 12);
        // fp32 sa output (contiguous n)
        float* dstf = sa + (size_t)b * Kq * Nq + (size_t)k * Nq + n0 + (ch << 4);
        *(float4*)(dstf)      = v0;
        *(float4*)(dstf + 4)  = v1;
        *(float4*)(dstf + 8)  = v2;
        *(float4*)(dstf + 12) = v3;
        // fp16 image
        uint4 oA, oB;
        oA.x = pk2h(v0.x * SA_SCALE, v0.y * SA_SCALE);
        oA.y = pk2h(v2.x * SA_SCALE, v2.y * SA_SCALE);
        oA.z = pk2h(v0.z * SA_SCALE, v0.w * SA_SCALE);
        oA.w = pk2h(v2.z * SA_SCALE, v2.w * SA_SCALE);
        oB.x = pk2h(v1.x * SA_SCALE, v1.y * SA_SCALE);
        oB.y = pk2h(v3.x * SA_SCALE, v3.y * SA_SCALE);
        oB.z = pk2h(v1.z * SA_SCALE, v1.w * SA_SCALE);
        oB.w = pk2h(v3.z * SA_SCALE, v3.w * SA_SCALE);
        size_t dstbase = ((size_t)((b * 64 + k) * 256 + (ntile << 4) + ch)) << 2;
        *(uint4*)&g_sa16b[dstbase]     = oA;   // qq 0,1
        *(uint4*)&g_sa16b[dstbase + 2] = oB;   // qq 2,3
        float sA = ((v0.x + v0.y) + (v0.z + v0.w)) + ((v1.x + v1.y) + (v1.z + v1.w));
        float sB = ((v2.x + v2.y) + (v2.z + v2.w)) + ((v3.x + v3.y) + (v3.z + v3.w));
        wssh[u] = sA + sB;
    }
    __syncthreads();
    if (tid < 64) {
        float s = 0.f;
#pragma unroll
        for (int c = 0; c < 16; ++c) s += wssh[tid * 16 + c];
        g_wsp[b][ntile][tid] = s;
    }
}

// ================= phase 2: wx[c,k] = sum_n x[c,n]*sa16[k,n]  (1-pass fp16) =====
__global__ __launch_bounds__(256, 2)
void phase2_kernel(const float* __restrict__ x) {
    extern __shared__ char smem[];
    const uint32_t sb = smem_u32(smem);
    const int tid = threadIdx.x;
    const int w = tid >> 5, lane = tid & 31;
    const int g = lane >> 2, q = lane & 3;
    const int c0w = w << 5;
    const int c0 = (int)blockIdx.x << 8;
    const int b  = blockIdx.y;
    const int seg = blockIdx.z;
    const int n0 = seg << 9;
    const float* xb = x + ((size_t)b * Cq + c0) * Nq + n0;

    float acc[2][8][4];
#pragma unroll
    for (int i = 0; i < 2; ++i)
#pragma unroll
        for (int j = 0; j < 8; ++j)
#pragma unroll
            for (int e = 0; e < 4; ++e) acc[i][j][e] = 0.f;

    auto fill = [&](int ch) {
        const uint32_t base = sb + (uint32_t)(ch & 3) * P2_BUF;
        const int nn = ch << 4;
#pragma unroll
        for (int it = 0; it < 4; ++it) {
            int u = tid + (it << 8);
            int row = u >> 2, sg2 = u & 3;
            CP16(base + (uint32_t)(row << 6) + (uint32_t)((sg2 ^ ((row >> 1) & 3)) << 4),
                 xb + (size_t)row * Nq + nn + (sg2 << 2));
        }
        if (tid < 128) {
            int node = tid >> 1, qq2 = tid & 1;
            CP16(base + P2_BOFF + (uint32_t)(tid << 4),
                 &g_sa16b[(((size_t)((b * 64 + node) * 256 + (seg << 5) + ch)) << 2) + (qq2 << 1)]);
        }
        CPCOMMIT();
    };

    auto gemm = [&](int buf) {
        const float* fA = (const float*)(smem + (uint32_t)buf * P2_BUF);
        const uint2* fB = (const uint2*)(smem + (uint32_t)buf * P2_BUF + P2_BOFF);
        unsigned aH[2][4];
#pragma unroll
        for (int i = 0; i < 2; ++i) {
            int r0 = c0w + (i << 4) + g;
            int r1 = r0 + 8;
            int k0 = ((r0 >> 1) & 3) << 2;
            int k1 = ((r1 >> 1) & 3) << 2;
            float2 p00 = *(const float2*)(fA + (r0 << 4) + ((2 * q) ^ k0));
            float2 p01 = *(const float2*)(fA + (r0 << 4) + ((2 * q + 8) ^ k0));
            float2 p10 = *(const float2*)(fA + (r1 << 4) + ((2 * q) ^ k1));
            float2 p11 = *(const float2*)(fA + (r1 << 4) + ((2 * q + 8) ^ k1));
            aH[i][0] = pk2h(p00.x, p00.y);
            aH[i][1] = pk2h(p10.x, p10.y);
            aH[i][2] = pk2h(p01.x, p01.y);
            aH[i][3] = pk2h(p11.x, p11.y);
        }
#pragma unroll
        for (int jb = 0; jb < 2; ++jb) {
            uint2 w2[4];
#pragma unroll
            for (int jj = 0; jj < 4; ++jj)
                w2[jj] = fB[(((((jb << 2) + jj) << 3) + g) << 2) + q];
#pragma unroll
            for (int jj = 0; jj < 4; ++jj) {
                unsigned bh[2] = { w2[jj].x, w2[jj].y };
                mmaH(acc[0][(jb << 2) + jj], aH[0], bh);
                mmaH(acc[1][(jb << 2) + jj], aH[1], bh);
            }
        }
    };

    fill(0); fill(1); fill(2);
    for (int ch = 0; ch < 32; ++ch) {
        if (ch + 2 < 32) { CPWAIT2(); } else if (ch + 1 < 32) { CPWAIT1(); } else { CPWAIT0(); }
        __syncthreads();
        if (ch + 3 < 32) fill(ch + 3);
        gemm(ch & 3);
    }

    // epilogue: unscale by 2^-11, scatter D[c,k] partials
    float* basep = &g_wx8[seg][b][0][0];
#pragma unroll
    for (int j = 0; j < 8; ++j) {
        int kc = (j << 3) + (q << 1);
#pragma unroll
        for (int i = 0; i < 2; ++i) {
            int cc = c0 + c0w + (i << 4) + g;
            basep[(size_t)kc * Cq + cc]           = acc[i][j][0] * SA_INV;
            basep[(size_t)(kc + 1) * Cq + cc]     = acc[i][j][1] * SA_INV;
            basep[(size_t)kc * Cq + cc + 8]       = acc[i][j][2] * SA_INV;
            basep[(size_t)(kc + 1) * Cq + cc + 8] = acc[i][j][3] * SA_INV;
        }
    }
}

// ================= phase 3: nodes + per-row l2norm (float4) =================
__global__ void phase3_kernel(const float* __restrict__ anchor) {
    const int bk = blockIdx.x;     // 1024
    const int b = bk >> 6, k = bk & 63;
    const int tid = threadIdx.x;   // 128
    float wsv = 0.f;
#pragma unroll
    for (int t = 0; t < 16; ++t) wsv += g_wsp[b][t][k];
    const float invw = 1.f / (wsv + 1e-9f);
    const int c = tid << 2;        // 4 consecutive c per thread
    float4 wx = make_float4(0.f, 0.f, 0.f, 0.f);
#pragma unroll
    for (int s = 0; s < 8; ++s) {
        float4 v = *(const float4*)&g_wx8[s][b][k][c];
        wx.x += v.x; wx.y += v.y; wx.z += v.z; wx.w += v.w;
    }
    float4 an = *(const float4*)&anchor[k * Cq + c];
    float4 iv = *(const float4*)&gInvS[k][c];
    float4 nd;
    nd.x = (wx.x - wsv * an.x) * iv.x * invw;
    nd.y = (wx.y - wsv * an.y) * iv.y * invw;
    nd.z = (wx.z - wsv * an.z) * iv.z * invw;
    nd.w = (wx.w - wsv * an.w) * iv.w * invw;
    float ssq = nd.x * nd.x + nd.y * nd.y + nd.z * nd.z + nd.w * nd.w;
#pragma unroll
    for (int off = 16; off; off >>= 1) ssq += __shfl_xor_sync(0xffffffffu, ssq, off);
    __shared__ float red[4];
    __shared__ float totsh;
    if ((tid & 31) == 0) red[tid >> 5] = ssq;
    __syncthreads();
    if (tid == 0) totsh = red[0] + red[1] + red[2] + red[3];
    __syncthreads();
    float total = totsh;
    float scale = 1.f / fmaxf(sqrtf(total), 1e-12f);
    float4 o;
    o.x = nd.x * scale; o.y = nd.y * scale; o.z = nd.z * scale; o.w = nd.w * scale;
    *(float4*)&g_nodes[b][k][c] = o;
    if (tid == 0) g_row[b][k] = total * scale * scale;
}

// ================= phase 4: global l2norm + output (float4) =================
__global__ void phase4_kernel(float* __restrict__ outflat) {
    const int b = blockIdx.x;      // 16
    const int tid = threadIdx.x;   // 256
    __shared__ float red[64];
    __shared__ float gsh;
    if (tid < 64) red[tid] = g_row[b][tid];
    __syncthreads();
    if (tid == 0) {
        float s = 0.f;
#pragma unroll
        for (int i = 0; i < 64; ++i) s += red[i];
        gsh = 1.f / fmaxf(sqrtf(s), 1e-12f);
    }
    __syncthreads();
    float g = gsh;
    const float4* np = (const float4*)&g_nodes[b][0][0];
    float4* op = (float4*)(outflat + (size_t)b * Kq * Cq);
#pragma unroll
    for (int it = 0; it < 32; ++it) {
        int i = tid + (it << 8);
        float4 v = np[i];
        v.x *= g; v.y *= g; v.z *= g; v.w *= g;
        op[i] = v;
    }
}

// ================= launch =================
extern "C" void kernel_launch(void* const* d_in, const int* in_sizes, int n_in,
                              void* d_out, int out_size) {
    const float* x      = (const float*)d_in[0];
    const float* anchor = (const float*)d_in[1];
    const float* sraw   = (const float*)d_in[2];
    float* outf = (float*)d_out;

    const int FLAT = Bq * Cq * Kq;      // 524288
    const int SA   = Bq * Kq * Nq;      // 4194304

    float* sa_dev = nullptr;
    cudaGetSymbolAddress((void**)&sa_dev, g_sa);
    float* nodes_dev = nullptr;
    cudaGetSymbolAddress((void**)&nodes_dev, g_nodes);

    float* sa_ptr;
    float* flat_ptr;
    if (out_size == FLAT) {
        flat_ptr = outf;
        sa_ptr = sa_dev;
    } else if (out_size == SA) {
        sa_ptr = outf;
        flat_ptr = nodes_dev;
    } else {
        flat_ptr = outf;
        sa_ptr = outf + FLAT;
    }

    static bool attr_done = false;
    if (!attr_done) {
        cudaFuncSetAttribute(phase1_kernel,
                             cudaFuncAttributeMaxDynamicSharedMemorySize, P1_SMEM);
        cudaFuncSetAttribute(phase2_kernel,
                             cudaFuncAttributeMaxDynamicSharedMemorySize, P2_SMEM);
        attr_done = true;
    }

    prep_kernel<<<Kq, 256>>>(anchor, sraw);
    phase1_kernel<<<dim3(Nq / 256, Bq), 256, P1_SMEM>>>(x, sa_ptr);
    phase2_kernel<<<dim3(Cq / 256, Bq, 8), 256, P2_SMEM>>>(x);
    phase3_kernel<<<Bq * Kq, 128>>>(anchor);
    phase4_kernel<<<Bq, 256>>>(flat_ptr);
}